// round 1
// baseline (speedup 1.0000x reference)
#include <cuda_runtime.h>
#include <math.h>

#define NMAX 20000
#define D 512

// ---------------- scratch (static device globals; no allocation) -------------
__device__ float g_H  [NMAX * D];
__device__ float g_X  [NMAX * D];
__device__ float g_AGG[NMAX * D];
__device__ float g_F  [NMAX * D];
__device__ float g_OUT[NMAX * D];
__device__ float g_RES[NMAX * D];
__device__ float g_norm[NMAX];
__device__ int   g_cnt [NMAX];

// ---------------- SGEMM: C[M,512] = scale * A[M,512] @ B (+C) (+bias) --------
// BT=true:  B is [512,512] accessed transposed  (out = A @ B^T)
// BT=false: B is [512,512] row-major            (out = A @ B)
template <bool BT, bool ACC, bool BIAS>
__global__ __launch_bounds__(256)
void sgemm(const float* __restrict__ A, const float* __restrict__ B,
           const float* __restrict__ bias, float* __restrict__ C,
           int M, float scale)
{
    constexpr int BM = 128, BN = 128, BK = 8;
    __shared__ float As[BK][BM];
    __shared__ float Bs[BK][BN];

    const int tid = threadIdx.x;
    const int bm  = blockIdx.y * BM;
    const int bn  = blockIdx.x * BN;
    const int tx  = (tid % 16) * 8;   // col offset of this thread's 8x8 tile
    const int ty  = (tid / 16) * 8;   // row offset

    // loader mapping (A tile and BT B tile: 128 rows x 8 k, float4 per thread)
    const int lRow = tid >> 1;
    const int lK   = (tid & 1) * 4;
    // loader mapping for row-major B tile: 8 k x 128 n
    const int bK   = tid >> 5;
    const int bN   = (tid & 31) * 4;

    float acc[8][8];
    #pragma unroll
    for (int i = 0; i < 8; i++)
        #pragma unroll
        for (int j = 0; j < 8; j++) acc[i][j] = 0.f;

    for (int k0 = 0; k0 < D; k0 += BK) {
        // --- load A tile (transposed into As[k][m]) ---
        {
            float4 av = make_float4(0.f, 0.f, 0.f, 0.f);
            int gr = bm + lRow;
            if (gr < M)
                av = *reinterpret_cast<const float4*>(A + (size_t)gr * D + k0 + lK);
            As[lK + 0][lRow] = av.x;
            As[lK + 1][lRow] = av.y;
            As[lK + 2][lRow] = av.z;
            As[lK + 3][lRow] = av.w;
        }
        // --- load B tile ---
        if (BT) {
            // B[n, k] layout; Bs[k][n] = B[(bn+n)*512 + k0+k]. n always < 512.
            float4 bv = *reinterpret_cast<const float4*>(B + (size_t)(bn + lRow) * D + k0 + lK);
            Bs[lK + 0][lRow] = bv.x;
            Bs[lK + 1][lRow] = bv.y;
            Bs[lK + 2][lRow] = bv.z;
            Bs[lK + 3][lRow] = bv.w;
        } else {
            float4 bv = *reinterpret_cast<const float4*>(B + (size_t)(k0 + bK) * D + bn + bN);
            *reinterpret_cast<float4*>(&Bs[bK][bN]) = bv;
        }
        __syncthreads();

        #pragma unroll
        for (int k = 0; k < BK; k++) {
            float ra[8], rb[8];
            *reinterpret_cast<float4*>(&ra[0]) = *reinterpret_cast<const float4*>(&As[k][ty]);
            *reinterpret_cast<float4*>(&ra[4]) = *reinterpret_cast<const float4*>(&As[k][ty + 4]);
            *reinterpret_cast<float4*>(&rb[0]) = *reinterpret_cast<const float4*>(&Bs[k][tx]);
            *reinterpret_cast<float4*>(&rb[4]) = *reinterpret_cast<const float4*>(&Bs[k][tx + 4]);
            #pragma unroll
            for (int i = 0; i < 8; i++)
                #pragma unroll
                for (int j = 0; j < 8; j++)
                    acc[i][j] += ra[i] * rb[j];
        }
        __syncthreads();
    }

    #pragma unroll
    for (int i = 0; i < 8; i++) {
        int gr = bm + ty + i;
        if (gr >= M) continue;
        #pragma unroll
        for (int j = 0; j < 8; j += 4) {
            int gc = bn + tx + j;
            float4 v;
            v.x = scale * acc[i][j + 0];
            v.y = scale * acc[i][j + 1];
            v.z = scale * acc[i][j + 2];
            v.w = scale * acc[i][j + 3];
            float4* cp = reinterpret_cast<float4*>(C + (size_t)gr * D + gc);
            if (ACC) {
                float4 c = *cp;
                v.x += c.x; v.y += c.y; v.z += c.z; v.w += c.w;
            }
            if (BIAS) {
                float4 bb = *reinterpret_cast<const float4*>(bias + gc);
                v.x += bb.x; v.y += bb.y; v.z += bb.z; v.w += bb.w;
            }
            *cp = v;
        }
    }
}

// ---------------- elementwise helpers ----------------------------------------
// out[row, :] = in[row, :] * norm[row] * mul     (float4 over rows of 512)
__global__ void scale_rows(const float* __restrict__ in, const float* __restrict__ norm,
                           float* __restrict__ out, float mul, long total4)
{
    long i = blockIdx.x * (long)blockDim.x + threadIdx.x;
    if (i >= total4) return;
    int row = (int)(i >> 7);                 // 128 float4 per row
    float s = __ldg(norm + row) * mul;
    float4 v = reinterpret_cast<const float4*>(in)[i];
    v.x *= s; v.y *= s; v.z *= s; v.w *= s;
    reinterpret_cast<float4*>(out)[i] = v;
}

__global__ void deg_kernel(const int* __restrict__ dst, int* __restrict__ cnt, int E)
{
    int i = blockIdx.x * blockDim.x + threadIdx.x;
    if (i < E) atomicAdd(cnt + __ldg(dst + i), 1);
}

__global__ void norm_kernel(const int* __restrict__ cnt, float* __restrict__ norm, int M)
{
    int i = blockIdx.x * blockDim.x + threadIdx.x;
    if (i < M) {
        float d = (float)cnt[i];
        norm[i] = rsqrtf(fmaxf(d, 1.0f));
    }
}

// AGG[dst[e], :] += X[src[e], :]   edge-parallel, float4 chunks, REDG atomics
__global__ void scatter_add(const float* __restrict__ X, const int* __restrict__ src,
                            const int* __restrict__ dst, float* __restrict__ AGG,
                            long total)
{
    long i = blockIdx.x * (long)blockDim.x + threadIdx.x;
    if (i >= total) return;
    int e = (int)(i >> 7);
    int c = ((int)i & 127) * 4;
    int s = __ldg(src + e);
    int d = __ldg(dst + e);
    float4 v = *reinterpret_cast<const float4*>(X + (size_t)s * D + c);
    float* p = AGG + (size_t)d * D + c;
    atomicAdd(p + 0, v.x);
    atomicAdd(p + 1, v.y);
    atomicAdd(p + 2, v.z);
    atomicAdd(p + 3, v.w);
}

// res = relu( beta*OUT + (1-beta)*(F + 0.1*H0) + bias[col] )
__global__ void combine(const float* __restrict__ OUT, const float* __restrict__ F,
                        const float* __restrict__ H0, const float* __restrict__ bias,
                        float* __restrict__ res, float beta, long total4)
{
    long i = blockIdx.x * (long)blockDim.x + threadIdx.x;
    if (i >= total4) return;
    int col = ((int)i & 127) * 4;
    float4 o = reinterpret_cast<const float4*>(OUT)[i];
    float4 f = reinterpret_cast<const float4*>(F)[i];
    float4 h = reinterpret_cast<const float4*>(H0)[i];
    float4 b = *reinterpret_cast<const float4*>(bias + col);
    float ob = 1.0f - beta;
    float4 r;
    r.x = fmaxf(beta * o.x + ob * (f.x + 0.1f * h.x) + b.x, 0.0f);
    r.y = fmaxf(beta * o.y + ob * (f.y + 0.1f * h.y) + b.y, 0.0f);
    r.z = fmaxf(beta * o.z + ob * (f.z + 0.1f * h.z) + b.z, 0.0f);
    r.w = fmaxf(beta * o.w + ob * (f.w + 0.1f * h.w) + b.w, 0.0f);
    reinterpret_cast<float4*>(res)[i] = r;
}

// ---------------- host-side orchestration ------------------------------------
static void run_layer(const float* h, const float* H0,
                      const float* w1, const float* w2, const float* b,
                      float beta, float* res,
                      float* X, float* AGG, float* F, float* OUT,
                      const float* NORM, const int* src, const int* dst,
                      int M, int E)
{
    long total4   = (long)M * (D / 4);
    long sc_total = (long)E * (D / 4);
    int  eb = 256;
    int  gb_el = (int)((total4 + eb - 1) / eb);
    int  gb_sc = (int)((sc_total + eb - 1) / eb);
    dim3 grid(D / 128, (M + 127) / 128);

    scale_rows<<<gb_el, eb>>>(h, NORM, X, 1.0f, total4);                // x = h * norm
    cudaMemsetAsync(AGG, 0, (size_t)M * D * sizeof(float));
    scatter_add<<<gb_sc, eb>>>(X, src, dst, AGG, sc_total);             // agg = segsum
    scale_rows<<<gb_el, eb>>>(AGG, NORM, F, 1.0f - 0.1f, total4);       // f = agg*norm*(1-alpha)
    sgemm<false, false, false><<<grid, 256>>>(F, w1, nullptr, OUT, M, 1.0f);   // OUT = f@w1
    sgemm<false, true,  false><<<grid, 256>>>(H0, w2, nullptr, OUT, M, 0.1f);  // OUT += alpha*h0@w2
    combine<<<gb_el, eb>>>(OUT, F, H0, b, res, beta, total4);
}

extern "C" void kernel_launch(void* const* d_in, const int* in_sizes, int n_in,
                              void* d_out, int out_size)
{
    const float* feat = (const float*)d_in[0];
    const int*   src  = (const int*)  d_in[1];
    const int*   dst  = (const int*)  d_in[2];
    const float* fc_w = (const float*)d_in[3];
    const float* fc_b = (const float*)d_in[4];
    const float* w1_1 = (const float*)d_in[5];
    const float* w2_1 = (const float*)d_in[6];
    const float* b_1  = (const float*)d_in[7];
    const float* w1_2 = (const float*)d_in[8];
    const float* w2_2 = (const float*)d_in[9];
    const float* b_2  = (const float*)d_in[10];
    float* out = (float*)d_out;

    int M = in_sizes[0] / D;
    int E = in_sizes[1];

    float *H, *X, *AGG, *F, *OUT, *RES, *NORM;
    int *CNT;
    cudaGetSymbolAddress((void**)&H,    g_H);
    cudaGetSymbolAddress((void**)&X,    g_X);
    cudaGetSymbolAddress((void**)&AGG,  g_AGG);
    cudaGetSymbolAddress((void**)&F,    g_F);
    cudaGetSymbolAddress((void**)&OUT,  g_OUT);
    cudaGetSymbolAddress((void**)&RES,  g_RES);
    cudaGetSymbolAddress((void**)&NORM, g_norm);
    cudaGetSymbolAddress((void**)&CNT,  g_cnt);

    dim3 grid(D / 128, (M + 127) / 128);

    // h = feat @ fc_w^T + fc_b
    sgemm<true, false, true><<<grid, 256>>>(feat, fc_w, fc_b, H, M, 1.0f);

    // degree + norm
    cudaMemsetAsync(CNT, 0, (size_t)M * sizeof(int));
    deg_kernel<<<(E + 255) / 256, 256>>>(dst, CNT, E);
    norm_kernel<<<(M + 255) / 256, 256>>>(CNT, NORM, M);

    const float beta1 = logf(1.0f / 1.0f + 1.0f);   // log(2)
    const float beta2 = logf(1.0f / 2.0f + 1.0f);   // log(1.5)

    run_layer(H,   H, w1_1, w2_1, b_1, beta1, RES, X, AGG, F, OUT, NORM, src, dst, M, E);
    run_layer(RES, H, w1_2, w2_2, b_2, beta2, out, X, AGG, F, OUT, NORM, src, dst, M, E);
}

// round 2
// speedup vs baseline: 1.3571x; 1.3571x over previous
#include <cuda_runtime.h>
#include <math.h>

#define NMAX 20000
#define EMAX 320000
#define D 512

// ---------------- scratch (static device globals; no allocation) -------------
__device__ float g_H   [NMAX * D];
__device__ float g_F   [NMAX * D];
__device__ float g_RES [NMAX * D];
__device__ float g_norm[NMAX];
__device__ int   g_cnt [NMAX];
__device__ int   g_off [NMAX + 1];
__device__ int   g_cur [NMAX + 1];
__device__ int   g_csr [EMAX];

// ================= CSR build ==================================================
__global__ void deg_kernel(const int* __restrict__ dst, int* __restrict__ cnt, int E)
{
    int i = blockIdx.x * blockDim.x + threadIdx.x;
    if (i < E) atomicAdd(cnt + __ldg(dst + i), 1);
}

__global__ void norm_kernel(const int* __restrict__ cnt, float* __restrict__ norm, int M)
{
    int i = blockIdx.x * blockDim.x + threadIdx.x;
    if (i < M) {
        float d = (float)cnt[i];
        norm[i] = rsqrtf(fmaxf(d, 1.0f));
    }
}

// single-block exclusive scan of cnt[0..n) -> off[0..n]
__global__ void scan_kernel(const int* __restrict__ cnt, int* __restrict__ off, int n)
{
    __shared__ int sh[1024];
    int t = threadIdx.x;
    int chunk = (n + 1023) >> 10;
    int base = t * chunk;
    int s = 0;
    for (int i = 0; i < chunk; i++) { int idx = base + i; if (idx < n) s += cnt[idx]; }
    sh[t] = s;
    __syncthreads();
    for (int d = 1; d < 1024; d <<= 1) {
        int v = (t >= d) ? sh[t - d] : 0;
        __syncthreads();
        sh[t] += v;
        __syncthreads();
    }
    int run = sh[t] - s;                    // exclusive prefix of this chunk
    for (int i = 0; i < chunk; i++) {
        int idx = base + i;
        if (idx < n) { off[idx] = run; run += cnt[idx]; }
    }
    if (t == 1023) off[n] = sh[1023];
}

__global__ void fill_kernel(const int* __restrict__ src, const int* __restrict__ dst,
                            int* __restrict__ cur, int* __restrict__ csr, int E)
{
    int i = blockIdx.x * blockDim.x + threadIdx.x;
    if (i < E) {
        int d = __ldg(dst + i);
        int p = atomicAdd(cur + d, 1);
        csr[p] = __ldg(src + i);
    }
}

// ================= aggregation (CSR gather-reduce, fused norms) ===============
// F[n,:] = 0.9 * norm[n] * sum_{e: dst=n} ( norm[src_e] * h[src_e, :] )
__global__ __launch_bounds__(128)
void agg_kernel(const float* __restrict__ h, const float* __restrict__ norm,
                const int* __restrict__ off, const int* __restrict__ csr,
                float* __restrict__ F)
{
    int node = blockIdx.x;
    int c    = threadIdx.x * 4;
    int s0 = __ldg(off + node);
    int s1 = __ldg(off + node + 1);
    float4 acc = make_float4(0.f, 0.f, 0.f, 0.f);
    int j = s0;
    for (; j + 1 < s1; j += 2) {
        int sA = __ldg(csr + j);
        int sB = __ldg(csr + j + 1);
        float wA = __ldg(norm + sA);
        float wB = __ldg(norm + sB);
        float4 vA = *reinterpret_cast<const float4*>(h + (size_t)sA * D + c);
        float4 vB = *reinterpret_cast<const float4*>(h + (size_t)sB * D + c);
        acc.x += wA * vA.x + wB * vB.x;
        acc.y += wA * vA.y + wB * vB.y;
        acc.z += wA * vA.z + wB * vB.z;
        acc.w += wA * vA.w + wB * vB.w;
    }
    if (j < s1) {
        int sA = __ldg(csr + j);
        float wA = __ldg(norm + sA);
        float4 vA = *reinterpret_cast<const float4*>(h + (size_t)sA * D + c);
        acc.x += wA * vA.x; acc.y += wA * vA.y;
        acc.z += wA * vA.z; acc.w += wA * vA.w;
    }
    float wn = __ldg(norm + node) * 0.9f;   // (1 - ALPHA)
    acc.x *= wn; acc.y *= wn; acc.z *= wn; acc.w *= wn;
    *reinterpret_cast<float4*>(F + (size_t)node * D + c) = acc;
}

// ================= GEMM: h = feat @ fc_w^T + fc_b =============================
__global__ __launch_bounds__(256)
void gemm_fc(const float* __restrict__ A, const float* __restrict__ B,
             const float* __restrict__ bias, float* __restrict__ C, int M)
{
    constexpr int BM = 128, BN = 128, BK = 8;
    __shared__ float As[BK][BM];
    __shared__ float Bs[BK][BN];

    const int tid = threadIdx.x;
    const int bm  = blockIdx.y * BM;
    const int bn  = blockIdx.x * BN;
    const int tx  = (tid % 16) * 8;
    const int ty  = (tid / 16) * 8;
    const int lRow = tid >> 1;
    const int lK   = (tid & 1) * 4;

    float acc[8][8];
    #pragma unroll
    for (int i = 0; i < 8; i++)
        #pragma unroll
        for (int j = 0; j < 8; j++) acc[i][j] = 0.f;

    for (int k0 = 0; k0 < D; k0 += BK) {
        {
            float4 av = make_float4(0.f, 0.f, 0.f, 0.f);
            int gr = bm + lRow;
            if (gr < M)
                av = *reinterpret_cast<const float4*>(A + (size_t)gr * D + k0 + lK);
            As[lK + 0][lRow] = av.x;
            As[lK + 1][lRow] = av.y;
            As[lK + 2][lRow] = av.z;
            As[lK + 3][lRow] = av.w;
        }
        {
            float4 bv = *reinterpret_cast<const float4*>(B + (size_t)(bn + lRow) * D + k0 + lK);
            Bs[lK + 0][lRow] = bv.x;
            Bs[lK + 1][lRow] = bv.y;
            Bs[lK + 2][lRow] = bv.z;
            Bs[lK + 3][lRow] = bv.w;
        }
        __syncthreads();
        #pragma unroll
        for (int k = 0; k < BK; k++) {
            float ra[8], rb[8];
            *reinterpret_cast<float4*>(&ra[0]) = *reinterpret_cast<const float4*>(&As[k][ty]);
            *reinterpret_cast<float4*>(&ra[4]) = *reinterpret_cast<const float4*>(&As[k][ty + 4]);
            *reinterpret_cast<float4*>(&rb[0]) = *reinterpret_cast<const float4*>(&Bs[k][tx]);
            *reinterpret_cast<float4*>(&rb[4]) = *reinterpret_cast<const float4*>(&Bs[k][tx + 4]);
            #pragma unroll
            for (int i = 0; i < 8; i++)
                #pragma unroll
                for (int j = 0; j < 8; j++)
                    acc[i][j] += ra[i] * rb[j];
        }
        __syncthreads();
    }

    #pragma unroll
    for (int i = 0; i < 8; i++) {
        int gr = bm + ty + i;
        if (gr >= M) continue;
        #pragma unroll
        for (int j = 0; j < 8; j += 4) {
            int gc = bn + tx + j;
            float4 bb = *reinterpret_cast<const float4*>(bias + gc);
            float4 v;
            v.x = acc[i][j + 0] + bb.x;
            v.y = acc[i][j + 1] + bb.y;
            v.z = acc[i][j + 2] + bb.z;
            v.w = acc[i][j + 3] + bb.w;
            *reinterpret_cast<float4*>(C + (size_t)gr * D + gc) = v;
        }
    }
}

// ================= fused layer GEMM ===========================================
// R = relu( beta*(F@W1 + 0.1*H0@W2) + (1-beta)*(F + 0.1*H0) + bias )
__global__ __launch_bounds__(256)
void gemm_layer(const float* __restrict__ F, const float* __restrict__ H0,
                const float* __restrict__ W1, const float* __restrict__ W2,
                const float* __restrict__ bias, float* __restrict__ R,
                int M, float beta)
{
    constexpr int BM = 128, BN = 128, BK = 8;
    __shared__ float As[BK][BM];
    __shared__ float Bs[BK][BN];

    const int tid = threadIdx.x;
    const int bm  = blockIdx.y * BM;
    const int bn  = blockIdx.x * BN;
    const int tx  = (tid % 16) * 8;
    const int ty  = (tid / 16) * 8;
    const int lRow = tid >> 1;
    const int lK   = (tid & 1) * 4;
    const int bK   = tid >> 5;
    const int bN   = (tid & 31) * 4;

    float acc[8][8];
    #pragma unroll
    for (int i = 0; i < 8; i++)
        #pragma unroll
        for (int j = 0; j < 8; j++) acc[i][j] = 0.f;

    for (int t = 0; t < 2 * (D / BK); t++) {
        const bool second = (t >= D / BK);
        const int k0 = (second ? (t - D / BK) : t) * BK;
        const float* A = second ? H0 : F;
        const float* B = second ? W2 : W1;
        const float bscale = second ? 0.1f : 1.0f;

        {
            float4 av = make_float4(0.f, 0.f, 0.f, 0.f);
            int gr = bm + lRow;
            if (gr < M)
                av = *reinterpret_cast<const float4*>(A + (size_t)gr * D + k0 + lK);
            As[lK + 0][lRow] = av.x;
            As[lK + 1][lRow] = av.y;
            As[lK + 2][lRow] = av.z;
            As[lK + 3][lRow] = av.w;
        }
        {
            float4 bv = *reinterpret_cast<const float4*>(B + (size_t)(k0 + bK) * D + bn + bN);
            bv.x *= bscale; bv.y *= bscale; bv.z *= bscale; bv.w *= bscale;
            *reinterpret_cast<float4*>(&Bs[bK][bN]) = bv;
        }
        __syncthreads();
        #pragma unroll
        for (int k = 0; k < BK; k++) {
            float ra[8], rb[8];
            *reinterpret_cast<float4*>(&ra[0]) = *reinterpret_cast<const float4*>(&As[k][ty]);
            *reinterpret_cast<float4*>(&ra[4]) = *reinterpret_cast<const float4*>(&As[k][ty + 4]);
            *reinterpret_cast<float4*>(&rb[0]) = *reinterpret_cast<const float4*>(&Bs[k][tx]);
            *reinterpret_cast<float4*>(&rb[4]) = *reinterpret_cast<const float4*>(&Bs[k][tx + 4]);
            #pragma unroll
            for (int i = 0; i < 8; i++)
                #pragma unroll
                for (int j = 0; j < 8; j++)
                    acc[i][j] += ra[i] * rb[j];
        }
        __syncthreads();
    }

    const float ob = 1.0f - beta;
    #pragma unroll
    for (int i = 0; i < 8; i++) {
        int gr = bm + ty + i;
        if (gr >= M) continue;
        #pragma unroll
        for (int j = 0; j < 8; j += 4) {
            int gc = bn + tx + j;
            float4 f  = *reinterpret_cast<const float4*>(F  + (size_t)gr * D + gc);
            float4 h0 = *reinterpret_cast<const float4*>(H0 + (size_t)gr * D + gc);
            float4 bb = *reinterpret_cast<const float4*>(bias + gc);
            float4 v;
            v.x = fmaxf(beta * acc[i][j + 0] + ob * (f.x + 0.1f * h0.x) + bb.x, 0.f);
            v.y = fmaxf(beta * acc[i][j + 1] + ob * (f.y + 0.1f * h0.y) + bb.y, 0.f);
            v.z = fmaxf(beta * acc[i][j + 2] + ob * (f.z + 0.1f * h0.z) + bb.z, 0.f);
            v.w = fmaxf(beta * acc[i][j + 3] + ob * (f.w + 0.1f * h0.w) + bb.w, 0.f);
            *reinterpret_cast<float4*>(R + (size_t)gr * D + gc) = v;
        }
    }
}

// ================= host orchestration =========================================
extern "C" void kernel_launch(void* const* d_in, const int* in_sizes, int n_in,
                              void* d_out, int out_size)
{
    const float* feat = (const float*)d_in[0];
    const int*   src  = (const int*)  d_in[1];
    const int*   dst  = (const int*)  d_in[2];
    const float* fc_w = (const float*)d_in[3];
    const float* fc_b = (const float*)d_in[4];
    const float* w1_1 = (const float*)d_in[5];
    const float* w2_1 = (const float*)d_in[6];
    const float* b_1  = (const float*)d_in[7];
    const float* w1_2 = (const float*)d_in[8];
    const float* w2_2 = (const float*)d_in[9];
    const float* b_2  = (const float*)d_in[10];
    float* out = (float*)d_out;

    int M = in_sizes[0] / D;
    int E = in_sizes[1];

    float *H, *F, *RES, *NORM;
    int *CNT, *OFF, *CUR, *CSR;
    cudaGetSymbolAddress((void**)&H,    g_H);
    cudaGetSymbolAddress((void**)&F,    g_F);
    cudaGetSymbolAddress((void**)&RES,  g_RES);
    cudaGetSymbolAddress((void**)&NORM, g_norm);
    cudaGetSymbolAddress((void**)&CNT,  g_cnt);
    cudaGetSymbolAddress((void**)&OFF,  g_off);
    cudaGetSymbolAddress((void**)&CUR,  g_cur);
    cudaGetSymbolAddress((void**)&CSR,  g_csr);

    dim3 grid(D / 128, (M + 127) / 128);

    // --- CSR build + norms (independent of GEMM below; interleave launches) ---
    cudaMemsetAsync(CNT, 0, (size_t)M * sizeof(int));
    deg_kernel <<<(E + 255) / 256, 256>>>(dst, CNT, E);

    // --- h = feat @ fc_w^T + fc_b ---
    gemm_fc<<<grid, 256>>>(feat, fc_w, fc_b, H, M);

    norm_kernel<<<(M + 255) / 256, 256>>>(CNT, NORM, M);
    scan_kernel<<<1, 1024>>>(CNT, OFF, M);
    cudaMemcpyAsync(CUR, OFF, (size_t)M * sizeof(int), cudaMemcpyDeviceToDevice);
    fill_kernel<<<(E + 255) / 256, 256>>>(src, dst, CUR, CSR, E);

    const float beta1 = logf(2.0f);    // log(1/1 + 1)
    const float beta2 = logf(1.5f);    // log(1/2 + 1)

    // --- layer 1 ---
    agg_kernel<<<M, 128>>>(H, NORM, OFF, CSR, F);
    gemm_layer<<<grid, 256>>>(F, H, w1_1, w2_1, b_1, RES, M, beta1);

    // --- layer 2 ---
    agg_kernel<<<M, 128>>>(RES, NORM, OFF, CSR, F);
    gemm_layer<<<grid, 256>>>(F, H, w1_2, w2_2, b_2, out, M, beta2);
}

// round 3
// speedup vs baseline: 3.3761x; 2.4876x over previous
#include <cuda_runtime.h>
#include <math.h>

#define NMAX 20000
#define EMAX 320000
#define D 512

// ---------------- scratch (static device globals; no allocation) -------------
__device__ float g_H   [NMAX * D];
__device__ float g_F   [NMAX * D];
__device__ float g_RES [NMAX * D];
__device__ float g_norm[NMAX];
__device__ int   g_cnt [NMAX];
__device__ int   g_off [NMAX + 1];
__device__ int   g_cur [NMAX + 1];
__device__ int   g_csr [EMAX];

// ================= CSR build ==================================================
__global__ void deg_kernel(const int* __restrict__ dst, int* __restrict__ cnt, int E)
{
    int i = blockIdx.x * blockDim.x + threadIdx.x;
    if (i < E) atomicAdd(cnt + __ldg(dst + i), 1);
}

__global__ void norm_kernel(const int* __restrict__ cnt, float* __restrict__ norm, int M)
{
    int i = blockIdx.x * blockDim.x + threadIdx.x;
    if (i < M) {
        float d = (float)cnt[i];
        norm[i] = rsqrtf(fmaxf(d, 1.0f));
    }
}

__global__ void scan_kernel(const int* __restrict__ cnt, int* __restrict__ off, int n)
{
    __shared__ int sh[1024];
    int t = threadIdx.x;
    int chunk = (n + 1023) >> 10;
    int base = t * chunk;
    int s = 0;
    for (int i = 0; i < chunk; i++) { int idx = base + i; if (idx < n) s += cnt[idx]; }
    sh[t] = s;
    __syncthreads();
    for (int d = 1; d < 1024; d <<= 1) {
        int v = (t >= d) ? sh[t - d] : 0;
        __syncthreads();
        sh[t] += v;
        __syncthreads();
    }
    int run = sh[t] - s;
    for (int i = 0; i < chunk; i++) {
        int idx = base + i;
        if (idx < n) { off[idx] = run; run += cnt[idx]; }
    }
    if (t == 1023) off[n] = sh[1023];
}

__global__ void fill_kernel(const int* __restrict__ src, const int* __restrict__ dst,
                            int* __restrict__ cur, int* __restrict__ csr, int E)
{
    int i = blockIdx.x * blockDim.x + threadIdx.x;
    if (i < E) {
        int d = __ldg(dst + i);
        int p = atomicAdd(cur + d, 1);
        csr[p] = __ldg(src + i);
    }
}

// ================= aggregation (CSR gather-reduce, fused norms) ===============
__global__ __launch_bounds__(128)
void agg_kernel(const float* __restrict__ h, const float* __restrict__ norm,
                const int* __restrict__ off, const int* __restrict__ csr,
                float* __restrict__ F)
{
    int node = blockIdx.x;
    int c    = threadIdx.x * 4;
    int s0 = __ldg(off + node);
    int s1 = __ldg(off + node + 1);
    float4 acc = make_float4(0.f, 0.f, 0.f, 0.f);
    int j = s0;
    for (; j + 1 < s1; j += 2) {
        int sA = __ldg(csr + j);
        int sB = __ldg(csr + j + 1);
        float wA = __ldg(norm + sA);
        float wB = __ldg(norm + sB);
        float4 vA = *reinterpret_cast<const float4*>(h + (size_t)sA * D + c);
        float4 vB = *reinterpret_cast<const float4*>(h + (size_t)sB * D + c);
        acc.x += wA * vA.x + wB * vB.x;
        acc.y += wA * vA.y + wB * vB.y;
        acc.z += wA * vA.z + wB * vB.z;
        acc.w += wA * vA.w + wB * vB.w;
    }
    if (j < s1) {
        int sA = __ldg(csr + j);
        float wA = __ldg(norm + sA);
        float4 vA = *reinterpret_cast<const float4*>(h + (size_t)sA * D + c);
        acc.x += wA * vA.x; acc.y += wA * vA.y;
        acc.z += wA * vA.z; acc.w += wA * vA.w;
    }
    float wn = __ldg(norm + node) * 0.9f;
    acc.x *= wn; acc.y *= wn; acc.z *= wn; acc.w *= wn;
    *reinterpret_cast<float4*>(F + (size_t)node * D + c) = acc;
}

// ================= tf32 tensor-core GEMM machinery ============================
__device__ __forceinline__ unsigned f2tf(float x)
{
    unsigned r;
    asm("cvt.rna.tf32.f32 %0, %1;" : "=r"(r) : "f"(x));
    return r;
}

__device__ __forceinline__ void mma8(float* c,
                                     unsigned a0, unsigned a1, unsigned a2, unsigned a3,
                                     unsigned b0, unsigned b1)
{
    asm volatile(
        "mma.sync.aligned.m16n8k8.row.col.f32.tf32.tf32.f32 "
        "{%0,%1,%2,%3},{%4,%5,%6,%7},{%8,%9},{%0,%1,%2,%3};"
        : "+f"(c[0]), "+f"(c[1]), "+f"(c[2]), "+f"(c[3])
        : "r"(a0), "r"(a1), "r"(a2), "r"(a3), "r"(b0), "r"(b1));
}

#define SA 20           // smem row stride (16 k + 4 pad) for [m][k] / [n][k] tiles
#define SBL 136         // smem row stride (128 n + 8 pad) for [k][n] tiles

// ---- gemm_fc: C = A[M,512] @ fc_w[512,512]^T + bias ------------------------
__global__ __launch_bounds__(256, 2)
void gemm_fc_tf32(const float* __restrict__ A, const float* __restrict__ Bw,
                  const float* __restrict__ bias, float* __restrict__ C, int M)
{
    __shared__ unsigned As[2][128 * SA];
    __shared__ unsigned Bs[2][128 * SA];

    const int tid  = threadIdx.x;
    const int lane = tid & 31;
    const int warp = tid >> 5;
    const int wm   = warp >> 2;       // 0..1
    const int wn   = warp & 3;        // 0..3
    const int bm   = blockIdx.y * 128;
    const int bn   = blockIdx.x * 128;
    const int grp  = lane >> 2;
    const int tig  = lane & 3;

    float acc[4][4][4] = {};
    float4 ra[2], rb[2];

    auto ldg = [&](int k0) {
        #pragma unroll
        for (int i = 0; i < 2; i++) {
            int c = tid + i * 256;
            int row = c >> 2, kq = c & 3;
            int gr = bm + row;
            ra[i] = (gr < M) ? *reinterpret_cast<const float4*>(A + (size_t)gr * D + k0 + kq * 4)
                             : make_float4(0.f, 0.f, 0.f, 0.f);
            rb[i] = *reinterpret_cast<const float4*>(Bw + (size_t)(bn + row) * D + k0 + kq * 4);
        }
    };
    auto sts = [&](int buf) {
        #pragma unroll
        for (int i = 0; i < 2; i++) {
            int c = tid + i * 256;
            int row = c >> 2, kq = c & 3;
            uint4 va = make_uint4(f2tf(ra[i].x), f2tf(ra[i].y), f2tf(ra[i].z), f2tf(ra[i].w));
            uint4 vb = make_uint4(f2tf(rb[i].x), f2tf(rb[i].y), f2tf(rb[i].z), f2tf(rb[i].w));
            *reinterpret_cast<uint4*>(&As[buf][row * SA + kq * 4]) = va;
            *reinterpret_cast<uint4*>(&Bs[buf][row * SA + kq * 4]) = vb;
        }
    };
    auto compute = [&](int buf) {
        #pragma unroll
        for (int kc = 0; kc < 2; kc++) {
            unsigned af[4][4], bf[4][2];
            #pragma unroll
            for (int mt = 0; mt < 4; mt++) {
                const unsigned* p = &As[buf][(wm * 64 + mt * 16) * SA + kc * 8];
                af[mt][0] = p[grp * SA + tig];
                af[mt][1] = p[(grp + 8) * SA + tig];
                af[mt][2] = p[grp * SA + tig + 4];
                af[mt][3] = p[(grp + 8) * SA + tig + 4];
            }
            #pragma unroll
            for (int nt = 0; nt < 4; nt++) {
                const unsigned* p = &Bs[buf][(wn * 32 + nt * 8 + grp) * SA + kc * 8];
                bf[nt][0] = p[tig];
                bf[nt][1] = p[tig + 4];
            }
            #pragma unroll
            for (int mt = 0; mt < 4; mt++)
                #pragma unroll
                for (int nt = 0; nt < 4; nt++)
                    mma8(acc[mt][nt], af[mt][0], af[mt][1], af[mt][2], af[mt][3],
                         bf[nt][0], bf[nt][1]);
        }
    };

    const int T = D / 16;     // 32
    ldg(0);
    sts(0);
    __syncthreads();
    for (int t = 0; t < T; t++) {
        int cur = t & 1;
        if (t + 1 < T) ldg((t + 1) * 16);
        compute(cur);
        if (t + 1 < T) {
            __syncthreads();
            sts(cur ^ 1);
            __syncthreads();
        }
    }

    #pragma unroll
    for (int mt = 0; mt < 4; mt++) {
        int gr0 = bm + wm * 64 + mt * 16 + grp;
        int gr1 = gr0 + 8;
        #pragma unroll
        for (int nt = 0; nt < 4; nt++) {
            int gc = bn + wn * 32 + nt * 8 + tig * 2;
            float2 bb = *reinterpret_cast<const float2*>(bias + gc);
            if (gr0 < M) {
                float2 v = make_float2(acc[mt][nt][0] + bb.x, acc[mt][nt][1] + bb.y);
                *reinterpret_cast<float2*>(C + (size_t)gr0 * D + gc) = v;
            }
            if (gr1 < M) {
                float2 v = make_float2(acc[mt][nt][2] + bb.x, acc[mt][nt][3] + bb.y);
                *reinterpret_cast<float2*>(C + (size_t)gr1 * D + gc) = v;
            }
        }
    }
}

// ---- gemm_layer: R = relu( beta*(F@W1 + 0.1*H0@W2) + (1-beta)*(F+0.1*H0) + b )
__global__ __launch_bounds__(256, 2)
void gemm_layer_tf32(const float* __restrict__ F, const float* __restrict__ H0,
                     const float* __restrict__ W1, const float* __restrict__ W2,
                     const float* __restrict__ bias, float* __restrict__ R,
                     int M, float beta)
{
    __shared__ unsigned As[2][128 * SA];
    __shared__ unsigned Bs[2][16 * SBL];

    const int tid  = threadIdx.x;
    const int lane = tid & 31;
    const int warp = tid >> 5;
    const int wm   = warp >> 2;
    const int wn   = warp & 3;
    const int bm   = blockIdx.y * 128;
    const int bn   = blockIdx.x * 128;
    const int grp  = lane >> 2;
    const int tig  = lane & 3;

    float acc[4][4][4] = {};
    float4 ra[2], rb[2];

    auto ldg = [&](int t) {
        const bool second = (t >= 32);
        const float* Ap = second ? H0 : F;
        const float* Bp = second ? W2 : W1;
        const float bs  = second ? 0.1f : 1.0f;
        const int k0 = (t & 31) * 16;
        #pragma unroll
        for (int i = 0; i < 2; i++) {
            int c = tid + i * 256;
            int row = c >> 2, kq = c & 3;
            int gr = bm + row;
            ra[i] = (gr < M) ? *reinterpret_cast<const float4*>(Ap + (size_t)gr * D + k0 + kq * 4)
                             : make_float4(0.f, 0.f, 0.f, 0.f);
            int kk = c >> 5, n4 = c & 31;
            float4 bv = *reinterpret_cast<const float4*>(Bp + (size_t)(k0 + kk) * D + bn + n4 * 4);
            bv.x *= bs; bv.y *= bs; bv.z *= bs; bv.w *= bs;
            rb[i] = bv;
        }
    };
    auto sts = [&](int buf) {
        #pragma unroll
        for (int i = 0; i < 2; i++) {
            int c = tid + i * 256;
            int row = c >> 2, kq = c & 3;
            uint4 va = make_uint4(f2tf(ra[i].x), f2tf(ra[i].y), f2tf(ra[i].z), f2tf(ra[i].w));
            *reinterpret_cast<uint4*>(&As[buf][row * SA + kq * 4]) = va;
            int kk = c >> 5, n4 = c & 31;
            uint4 vb = make_uint4(f2tf(rb[i].x), f2tf(rb[i].y), f2tf(rb[i].z), f2tf(rb[i].w));
            *reinterpret_cast<uint4*>(&Bs[buf][kk * SBL + n4 * 4]) = vb;
        }
    };
    auto compute = [&](int buf) {
        #pragma unroll
        for (int kc = 0; kc < 2; kc++) {
            unsigned af[4][4], bf[4][2];
            #pragma unroll
            for (int mt = 0; mt < 4; mt++) {
                const unsigned* p = &As[buf][(wm * 64 + mt * 16) * SA + kc * 8];
                af[mt][0] = p[grp * SA + tig];
                af[mt][1] = p[(grp + 8) * SA + tig];
                af[mt][2] = p[grp * SA + tig + 4];
                af[mt][3] = p[(grp + 8) * SA + tig + 4];
            }
            #pragma unroll
            for (int nt = 0; nt < 4; nt++) {
                const unsigned* p = &Bs[buf][(kc * 8 + tig) * SBL + wn * 32 + nt * 8 + grp];
                bf[nt][0] = p[0];
                bf[nt][1] = p[4 * SBL];
            }
            #pragma unroll
            for (int mt = 0; mt < 4; mt++)
                #pragma unroll
                for (int nt = 0; nt < 4; nt++)
                    mma8(acc[mt][nt], af[mt][0], af[mt][1], af[mt][2], af[mt][3],
                         bf[nt][0], bf[nt][1]);
        }
    };

    const int T = 2 * (D / 16);   // 64
    ldg(0);
    sts(0);
    __syncthreads();
    for (int t = 0; t < T; t++) {
        int cur = t & 1;
        if (t + 1 < T) ldg(t + 1);
        compute(cur);
        if (t + 1 < T) {
            __syncthreads();
            sts(cur ^ 1);
            __syncthreads();
        }
    }

    const float ob = 1.0f - beta;
    #pragma unroll
    for (int mt = 0; mt < 4; mt++) {
        int gr[2];
        gr[0] = bm + wm * 64 + mt * 16 + grp;
        gr[1] = gr[0] + 8;
        #pragma unroll
        for (int nt = 0; nt < 4; nt++) {
            int gc = bn + wn * 32 + nt * 8 + tig * 2;
            float2 bb = *reinterpret_cast<const float2*>(bias + gc);
            #pragma unroll
            for (int h = 0; h < 2; h++) {
                if (gr[h] >= M) continue;
                size_t base = (size_t)gr[h] * D + gc;
                float2 f  = *reinterpret_cast<const float2*>(F  + base);
                float2 h0 = *reinterpret_cast<const float2*>(H0 + base);
                float2 v;
                v.x = fmaxf(beta * acc[mt][nt][2 * h + 0] + ob * (f.x + 0.1f * h0.x) + bb.x, 0.f);
                v.y = fmaxf(beta * acc[mt][nt][2 * h + 1] + ob * (f.y + 0.1f * h0.y) + bb.y, 0.f);
                *reinterpret_cast<float2*>(R + base) = v;
            }
        }
    }
}

// ================= host orchestration =========================================
extern "C" void kernel_launch(void* const* d_in, const int* in_sizes, int n_in,
                              void* d_out, int out_size)
{
    const float* feat = (const float*)d_in[0];
    const int*   src  = (const int*)  d_in[1];
    const int*   dst  = (const int*)  d_in[2];
    const float* fc_w = (const float*)d_in[3];
    const float* fc_b = (const float*)d_in[4];
    const float* w1_1 = (const float*)d_in[5];
    const float* w2_1 = (const float*)d_in[6];
    const float* b_1  = (const float*)d_in[7];
    const float* w1_2 = (const float*)d_in[8];
    const float* w2_2 = (const float*)d_in[9];
    const float* b_2  = (const float*)d_in[10];
    float* out = (float*)d_out;

    int M = in_sizes[0] / D;
    int E = in_sizes[1];

    float *H, *F, *RES, *NORM;
    int *CNT, *OFF, *CUR, *CSR;
    cudaGetSymbolAddress((void**)&H,    g_H);
    cudaGetSymbolAddress((void**)&F,    g_F);
    cudaGetSymbolAddress((void**)&RES,  g_RES);
    cudaGetSymbolAddress((void**)&NORM, g_norm);
    cudaGetSymbolAddress((void**)&CNT,  g_cnt);
    cudaGetSymbolAddress((void**)&OFF,  g_off);
    cudaGetSymbolAddress((void**)&CUR,  g_cur);
    cudaGetSymbolAddress((void**)&CSR,  g_csr);

    dim3 grid(D / 128, (M + 127) / 128);

    cudaMemsetAsync(CNT, 0, (size_t)M * sizeof(int));
    deg_kernel<<<(E + 255) / 256, 256>>>(dst, CNT, E);

    gemm_fc_tf32<<<grid, 256>>>(feat, fc_w, fc_b, H, M);

    norm_kernel<<<(M + 255) / 256, 256>>>(CNT, NORM, M);
    scan_kernel<<<1, 1024>>>(CNT, OFF, M);
    cudaMemcpyAsync(CUR, OFF, (size_t)M * sizeof(int), cudaMemcpyDeviceToDevice);
    fill_kernel<<<(E + 255) / 256, 256>>>(src, dst, CUR, CSR, E);

    const float beta1 = logf(2.0f);
    const float beta2 = logf(1.5f);

    agg_kernel<<<M, 128>>>(H, NORM, OFF, CSR, F);
    gemm_layer_tf32<<<grid, 256>>>(F, H, w1_1, w2_1, b_1, RES, M, beta1);

    agg_kernel<<<M, 128>>>(RES, NORM, OFF, CSR, F);
    gemm_layer_tf32<<<grid, 256>>>(F, H, w1_2, w2_2, b_2, out, M, beta2);
}

// round 5
// speedup vs baseline: 3.8898x; 1.1522x over previous
#include <cuda_runtime.h>
#include <cstdint>
#include <math.h>

#define NMAX 20000
#define EMAX 320000
#define D 512

// ---------------- scratch (static device globals; no allocation) -------------
__device__ float g_H   [NMAX * D];
__device__ float g_F   [NMAX * D];
__device__ float g_RES [NMAX * D];
__device__ float g_WB  [5 * D * D];     // pre-rounded tf32 weights
__device__ float g_norm[NMAX];
__device__ int   g_cnt [NMAX];
__device__ int   g_off [NMAX + 1];
__device__ int   g_cur [NMAX + 1];
__device__ int   g_csr [EMAX];

// ================= small helpers ==============================================
__device__ __forceinline__ unsigned f2tf(float x)
{
    unsigned r;
    asm("cvt.rna.tf32.f32 %0, %1;" : "=r"(r) : "f"(x));
    return r;
}
__device__ __forceinline__ float rndtf(float x) { return __uint_as_float(f2tf(x)); }

__device__ __forceinline__ void cp16(uint32_t dst, const float* src, int bytes)
{
    asm volatile("cp.async.cg.shared.global [%0], [%1], 16, %2;"
                 :: "r"(dst), "l"(src), "r"(bytes));
}
__device__ __forceinline__ void cp_commit()
{
    asm volatile("cp.async.commit_group;");
}
template <int N> __device__ __forceinline__ void cp_wait()
{
    asm volatile("cp.async.wait_group %0;" :: "n"(N));
}

__device__ __forceinline__ void mma8(float* c,
                                     unsigned a0, unsigned a1, unsigned a2, unsigned a3,
                                     unsigned b0, unsigned b1)
{
    asm volatile(
        "mma.sync.aligned.m16n8k8.row.col.f32.tf32.tf32.f32 "
        "{%0,%1,%2,%3},{%4,%5,%6,%7},{%8,%9},{%0,%1,%2,%3};"
        : "+f"(c[0]), "+f"(c[1]), "+f"(c[2]), "+f"(c[3])
        : "r"(a0), "r"(a1), "r"(a2), "r"(a3), "r"(b0), "r"(b1));
}

// ================= weight prep (round to tf32, bake 0.1 into W2) =============
__global__ void prep_w(const float* __restrict__ fcw, const float* __restrict__ w11,
                       const float* __restrict__ w21, const float* __restrict__ w12,
                       const float* __restrict__ w22, float* __restrict__ wb)
{
    int i = blockIdx.x * blockDim.x + threadIdx.x;
    if (i >= 5 * D * D) return;
    int m = i >> 18;
    int o = i & (D * D - 1);
    const float* s;
    float sc = 1.0f;
    if      (m == 0)  s = fcw;
    else if (m == 1)  s = w11;
    else if (m == 2) { s = w21; sc = 0.1f; }
    else if (m == 3)  s = w12;
    else             { s = w22; sc = 0.1f; }
    wb[i] = rndtf(s[o] * sc);
}

__global__ void round_mat(const float* __restrict__ in, float* __restrict__ out, long n4)
{
    long i = blockIdx.x * (long)blockDim.x + threadIdx.x;
    if (i >= n4) return;
    float4 v = reinterpret_cast<const float4*>(in)[i];
    v.x = rndtf(v.x); v.y = rndtf(v.y); v.z = rndtf(v.z); v.w = rndtf(v.w);
    reinterpret_cast<float4*>(out)[i] = v;
}

// ================= CSR build ==================================================
__global__ void deg_kernel(const int* __restrict__ dst, int* __restrict__ cnt, int E)
{
    int i = blockIdx.x * blockDim.x + threadIdx.x;
    if (i < E) atomicAdd(cnt + __ldg(dst + i), 1);
}

// scan + cur init + norm, fused
__global__ void scan_kernel(const int* __restrict__ cnt, int* __restrict__ off,
                            int* __restrict__ cur, float* __restrict__ norm, int n)
{
    __shared__ int sh[1024];
    int t = threadIdx.x;
    int chunk = (n + 1023) >> 10;
    int base = t * chunk;
    int s = 0;
    for (int i = 0; i < chunk; i++) { int idx = base + i; if (idx < n) s += cnt[idx]; }
    sh[t] = s;
    __syncthreads();
    for (int d = 1; d < 1024; d <<= 1) {
        int v = (t >= d) ? sh[t - d] : 0;
        __syncthreads();
        sh[t] += v;
        __syncthreads();
    }
    int run = sh[t] - s;
    for (int i = 0; i < chunk; i++) {
        int idx = base + i;
        if (idx < n) {
            int c = cnt[idx];
            off[idx] = run;
            cur[idx] = run;
            norm[idx] = rsqrtf(fmaxf((float)c, 1.0f));
            run += c;
        }
    }
    if (t == 1023) off[n] = sh[1023];
}

__global__ void fill_kernel(const int* __restrict__ src, const int* __restrict__ dst,
                            int* __restrict__ cur, int* __restrict__ csr, int E)
{
    int i = blockIdx.x * blockDim.x + threadIdx.x;
    if (i < E) {
        int d = __ldg(dst + i);
        int p = atomicAdd(cur + d, 1);
        csr[p] = __ldg(src + i);
    }
}

// ================= aggregation (CSR gather-reduce, fused norms) ===============
// F[n,:] = rndtf( 0.9 * norm[n] * sum_{e: dst=n} norm[src_e] * h[src_e, :] )
__global__ __launch_bounds__(128)
void agg_kernel(const float* __restrict__ h, const float* __restrict__ norm,
                const int* __restrict__ off, const int* __restrict__ csr,
                float* __restrict__ F)
{
    int node = blockIdx.x;
    int c    = threadIdx.x * 4;
    int s0 = __ldg(off + node);
    int s1 = __ldg(off + node + 1);
    float4 acc = make_float4(0.f, 0.f, 0.f, 0.f);
    int j = s0;
    for (; j + 3 < s1; j += 4) {
        int   si[4];
        float wi[4];
        #pragma unroll
        for (int u = 0; u < 4; u++) { si[u] = __ldg(csr + j + u); }
        #pragma unroll
        for (int u = 0; u < 4; u++) { wi[u] = __ldg(norm + si[u]); }
        float4 v[4];
        #pragma unroll
        for (int u = 0; u < 4; u++)
            v[u] = *reinterpret_cast<const float4*>(h + (size_t)si[u] * D + c);
        #pragma unroll
        for (int u = 0; u < 4; u++) {
            acc.x += wi[u] * v[u].x;
            acc.y += wi[u] * v[u].y;
            acc.z += wi[u] * v[u].z;
            acc.w += wi[u] * v[u].w;
        }
    }
    for (; j < s1; j++) {
        int sA = __ldg(csr + j);
        float wA = __ldg(norm + sA);
        float4 vA = *reinterpret_cast<const float4*>(h + (size_t)sA * D + c);
        acc.x += wA * vA.x; acc.y += wA * vA.y;
        acc.z += wA * vA.z; acc.w += wA * vA.w;
    }
    float wn = __ldg(norm + node) * 0.9f;
    float4 r;
    r.x = rndtf(acc.x * wn);
    r.y = rndtf(acc.y * wn);
    r.z = rndtf(acc.z * wn);
    r.w = rndtf(acc.w * wn);
    *reinterpret_cast<float4*>(F + (size_t)node * D + c) = r;
}

// ================= tf32 tensor-core GEMMs with cp.async ======================
// RK tile: 128 rows x 16 k, 16B chunks, chunk swizzle c' = c ^ ((row>>1)&3).
// stage elems: 2048 (A), B_fc same; B_layer KN: 16 x 136 elems = 2176.
#define STG 3

// ---- gemm_fc: H = rndtf( A[M,512] @ Wt[512,512](n-major) + bias ) -----------
__global__ __launch_bounds__(256, 2)
void gemm_fc_tc(const float* __restrict__ A, const float* __restrict__ Bw,
                const float* __restrict__ bias, float* __restrict__ C, int M)
{
    extern __shared__ unsigned sm[];
    const int tid = threadIdx.x, lane = tid & 31, warp = tid >> 5;
    const int wm = warp >> 2, wn = warp & 3;
    const int bm = blockIdx.y * 128, bn = blockIdx.x * 128;
    const int grp = lane >> 2, tig = lane & 3;
    const uint32_t smb = (uint32_t)__cvta_generic_to_shared(sm);

    float acc[4][4][4] = {};

    const int lr   = tid >> 1;          // row 0..127
    const int lc0  = (tid & 1) * 2;     // chunk 0 or 2
    const int lkey = (lr >> 1) & 3;
    const int arow = bm + lr;
    const int avld = (arow < M) ? 16 : 0;
    const float* Abase = A + (size_t)(avld ? arow : 0) * D + lc0 * 4;
    const float* Bbase = Bw + (size_t)(bn + lr) * D + lc0 * 4;
    const uint32_t dA0 = smb + (lr * 16 + ((lc0 ^ lkey) << 2)) * 4;
    const uint32_t dA1 = smb + (lr * 16 + (((lc0 + 1) ^ lkey) << 2)) * 4;
    const uint32_t dB0 = dA0 + STG * 2048 * 4;
    const uint32_t dB1 = dA1 + STG * 2048 * 4;

    auto issue = [&](int stage, int k0) {
        uint32_t so = (uint32_t)stage * 2048u * 4u;
        cp16(dA0 + so, Abase + k0, avld);
        cp16(dA1 + so, Abase + k0 + 4, avld);
        cp16(dB0 + so, Bbase + k0, 16);
        cp16(dB1 + so, Bbase + k0 + 4, 16);
        cp_commit();
    };

    // fragment address precompute
    int abase[4], akey[4], bbase[4], bkey[4];
    #pragma unroll
    for (int mt = 0; mt < 4; mt++) {
        int r = wm * 64 + mt * 16 + grp;
        akey[mt]  = (r >> 1) & 3;
        abase[mt] = r * 16 + tig;
    }
    #pragma unroll
    for (int nt = 0; nt < 4; nt++) {
        int r = wn * 32 + nt * 8 + grp;
        bkey[nt]  = (r >> 1) & 3;
        bbase[nt] = r * 16 + tig;
    }

    auto compute = [&](int stage) {
        const unsigned* sA = sm + stage * 2048;
        const unsigned* sB = sA + STG * 2048;
        #pragma unroll
        for (int kc = 0; kc < 2; kc++) {
            unsigned af[4][4], bf[4][2];
            #pragma unroll
            for (int mt = 0; mt < 4; mt++) {
                int c0 = ((2 * kc) ^ akey[mt]) << 2;
                int c1 = ((2 * kc + 1) ^ akey[mt]) << 2;
                af[mt][0] = sA[abase[mt] + c0];
                af[mt][1] = sA[abase[mt] + 128 + c0];
                af[mt][2] = sA[abase[mt] + c1];
                af[mt][3] = sA[abase[mt] + 128 + c1];
            }
            #pragma unroll
            for (int nt = 0; nt < 4; nt++) {
                bf[nt][0] = sB[bbase[nt] + (((2 * kc) ^ bkey[nt]) << 2)];
                bf[nt][1] = sB[bbase[nt] + (((2 * kc + 1) ^ bkey[nt]) << 2)];
            }
            #pragma unroll
            for (int mt = 0; mt < 4; mt++)
                #pragma unroll
                for (int nt = 0; nt < 4; nt++)
                    mma8(acc[mt][nt], af[mt][0], af[mt][1], af[mt][2], af[mt][3],
                         bf[nt][0], bf[nt][1]);
        }
    };

    const int T = D / 16;     // 32
    issue(0, 0);
    issue(1, 16);
    for (int t = 0; t < T; t++) {
        cp_wait<STG - 2>();
        __syncthreads();
        if (t + STG - 1 < T) issue((t + STG - 1) % STG, (t + STG - 1) * 16);
        else                 cp_commit();
        compute(t % STG);
    }

    #pragma unroll
    for (int mt = 0; mt < 4; mt++) {
        int gr0 = bm + wm * 64 + mt * 16 + grp;
        int gr1 = gr0 + 8;
        #pragma unroll
        for (int nt = 0; nt < 4; nt++) {
            int gc = bn + wn * 32 + nt * 8 + tig * 2;
            float2 bb = *reinterpret_cast<const float2*>(bias + gc);
            if (gr0 < M) {
                float2 v = make_float2(rndtf(acc[mt][nt][0] + bb.x),
                                       rndtf(acc[mt][nt][1] + bb.y));
                *reinterpret_cast<float2*>(C + (size_t)gr0 * D + gc) = v;
            }
            if (gr1 < M) {
                float2 v = make_float2(rndtf(acc[mt][nt][2] + bb.x),
                                       rndtf(acc[mt][nt][3] + bb.y));
                *reinterpret_cast<float2*>(C + (size_t)gr1 * D + gc) = v;
            }
        }
    }
}

// ---- gemm_layer: R = relu( beta*(F@W1 + H0@W2s) + (1-beta)*(F+0.1*H0) + b ) -
// W2s already scaled by 0.1 in prep. B tiles row-major [k][n], stride 136.
__global__ __launch_bounds__(256, 2)
void gemm_layer_tc(const float* __restrict__ F, const float* __restrict__ H0,
                   const float* __restrict__ W1, const float* __restrict__ W2s,
                   const float* __restrict__ bias, float* __restrict__ R,
                   int M, float beta)
{
    extern __shared__ unsigned sm[];
    const int tid = threadIdx.x, lane = tid & 31, warp = tid >> 5;
    const int wm = warp >> 2, wn = warp & 3;
    const int bm = blockIdx.y * 128, bn = blockIdx.x * 128;
    const int grp = lane >> 2, tig = lane & 3;
    const uint32_t smb = (uint32_t)__cvta_generic_to_shared(sm);

    float acc[4][4][4] = {};

    const int lr   = tid >> 1;
    const int lc0  = (tid & 1) * 2;
    const int lkey = (lr >> 1) & 3;
    const int arow = bm + lr;
    const int avld = (arow < M) ? 16 : 0;
    const size_t aoff = (size_t)(avld ? arow : 0) * D + lc0 * 4;
    const uint32_t dA0 = smb + (lr * 16 + ((lc0 ^ lkey) << 2)) * 4;
    const uint32_t dA1 = smb + (lr * 16 + (((lc0 + 1) ^ lkey) << 2)) * 4;
    // B loader: 512 chunks of 16B per tile; thread -> 2 chunks
    const int bk  = tid >> 4;           // k row 0..15
    const int bc  = (tid & 15) * 2;     // chunk 0..30 (step 2)
    const size_t boff = (size_t)bk * D + bn + bc * 4;
    const uint32_t dBb = smb + STG * 2048u * 4u + (uint32_t)(bk * 136 + bc * 4) * 4u;

    auto issue = [&](int stage, int t) {
        const bool second = (t >= 32);
        const float* Ap = second ? H0 : F;
        const float* Bp = second ? W2s : W1;
        const int k0 = (t & 31) * 16;
        uint32_t soA = (uint32_t)stage * 2048u * 4u;
        cp16(dA0 + soA, Ap + aoff + k0, avld);
        cp16(dA1 + soA, Ap + aoff + k0 + 4, avld);
        uint32_t soB = (uint32_t)stage * 2176u * 4u;
        const float* bg = Bp + boff + (size_t)k0 * D;
        cp16(dBb + soB,      bg,     16);
        cp16(dBb + soB + 16, bg + 4, 16);
        cp_commit();
    };

    int abase[4], akey[4], bbase[4];
    #pragma unroll
    for (int mt = 0; mt < 4; mt++) {
        int r = wm * 64 + mt * 16 + grp;
        akey[mt]  = (r >> 1) & 3;
        abase[mt] = r * 16 + tig;
    }
    #pragma unroll
    for (int nt = 0; nt < 4; nt++)
        bbase[nt] = wn * 32 + nt * 8 + grp;

    auto compute = [&](int stage) {
        const unsigned* sA = sm + stage * 2048;
        const unsigned* sB = sm + STG * 2048 + stage * 2176;
        #pragma unroll
        for (int kc = 0; kc < 2; kc++) {
            unsigned af[4][4], bf[4][2];
            #pragma unroll
            for (int mt = 0; mt < 4; mt++) {
                int c0 = ((2 * kc) ^ akey[mt]) << 2;
                int c1 = ((2 * kc + 1) ^ akey[mt]) << 2;
                af[mt][0] = sA[abase[mt] + c0];
                af[mt][1] = sA[abase[mt] + 128 + c0];
                af[mt][2] = sA[abase[mt] + c1];
                af[mt][3] = sA[abase[mt] + 128 + c1];
            }
            const unsigned* bk0 = sB + (kc * 8 + tig) * 136;
            #pragma unroll
            for (int nt = 0; nt < 4; nt++) {
                bf[nt][0] = bk0[bbase[nt]];
                bf[nt][1] = bk0[4 * 136 + bbase[nt]];
            }
            #pragma unroll
            for (int mt = 0; mt < 4; mt++)
                #pragma unroll
                for (int nt = 0; nt < 4; nt++)
                    mma8(acc[mt][nt], af[mt][0], af[mt][1], af[mt][2], af[mt][3],
                         bf[nt][0], bf[nt][1]);
        }
    };

    const int T = 2 * (D / 16);   // 64
    issue(0, 0);
    issue(1, 1);
    for (int t = 0; t < T; t++) {
        cp_wait<STG - 2>();
        __syncthreads();
        if (t + STG - 1 < T) issue((t + STG - 1) % STG, t + STG - 1);
        else                 cp_commit();
        compute(t % STG);
    }

    const float ob = 1.0f - beta;
    #pragma unroll
    for (int mt = 0; mt < 4; mt++) {
        int gr[2];
        gr[0] = bm + wm * 64 + mt * 16 + grp;
        gr[1] = gr[0] + 8;
        #pragma unroll
        for (int nt = 0; nt < 4; nt++) {
            int gc = bn + wn * 32 + nt * 8 + tig * 2;
            float2 bb = *reinterpret_cast<const float2*>(bias + gc);
            #pragma unroll
            for (int hh = 0; hh < 2; hh++) {
                if (gr[hh] >= M) continue;
                size_t base = (size_t)gr[hh] * D + gc;
                float2 f  = *reinterpret_cast<const float2*>(F  + base);
                float2 h0 = *reinterpret_cast<const float2*>(H0 + base);
                float2 v;
                v.x = fmaxf(beta * acc[mt][nt][2 * hh + 0] + ob * (f.x + 0.1f * h0.x) + bb.x, 0.f);
                v.y = fmaxf(beta * acc[mt][nt][2 * hh + 1] + ob * (f.y + 0.1f * h0.y) + bb.y, 0.f);
                *reinterpret_cast<float2*>(R + base) = v;
            }
        }
    }
}

// ================= host orchestration =========================================
extern "C" void kernel_launch(void* const* d_in, const int* in_sizes, int n_in,
                              void* d_out, int out_size)
{
    const float* feat = (const float*)d_in[0];
    const int*   src  = (const int*)  d_in[1];
    const int*   dst  = (const int*)  d_in[2];
    const float* fc_w = (const float*)d_in[3];
    const float* fc_b = (const float*)d_in[4];
    const float* w1_1 = (const float*)d_in[5];
    const float* w2_1 = (const float*)d_in[6];
    const float* b_1  = (const float*)d_in[7];
    const float* w1_2 = (const float*)d_in[8];
    const float* w2_2 = (const float*)d_in[9];
    const float* b_2  = (const float*)d_in[10];
    float* out = (float*)d_out;

    int M = in_sizes[0] / D;
    int E = in_sizes[1];

    float *H, *F, *RES, *WB, *NORM;
    int *CNT, *OFF, *CUR, *CSR;
    cudaGetSymbolAddress((void**)&H,    g_H);
    cudaGetSymbolAddress((void**)&F,    g_F);
    cudaGetSymbolAddress((void**)&RES,  g_RES);
    cudaGetSymbolAddress((void**)&WB,   g_WB);
    cudaGetSymbolAddress((void**)&NORM, g_norm);
    cudaGetSymbolAddress((void**)&CNT,  g_cnt);
    cudaGetSymbolAddress((void**)&OFF,  g_off);
    cudaGetSymbolAddress((void**)&CUR,  g_cur);
    cudaGetSymbolAddress((void**)&CSR,  g_csr);

    const int smem_fc    = STG * 2048 * 2 * 4;            // 49152
    const int smem_layer = STG * (2048 + 2176) * 4;       // 50688
    cudaFuncSetAttribute(gemm_fc_tc,    cudaFuncAttributeMaxDynamicSharedMemorySize, smem_fc);
    cudaFuncSetAttribute(gemm_layer_tc, cudaFuncAttributeMaxDynamicSharedMemorySize, smem_layer);

    dim3 grid(D / 128, (M + 127) / 128);

    // CSR + prep
    cudaMemsetAsync(CNT, 0, (size_t)M * sizeof(int));
    deg_kernel<<<(E + 255) / 256, 256>>>(dst, CNT, E);
    prep_w<<<(5 * D * D + 255) / 256, 256>>>(fc_w, w1_1, w2_1, w1_2, w2_2, WB);
    round_mat<<<(int)(((long)M * (D / 4) + 255) / 256), 256>>>(feat, RES, (long)M * (D / 4));
    scan_kernel<<<1, 1024>>>(CNT, OFF, CUR, NORM, M);

    // h = rndtf(feat @ fc_w^T + fc_b)
    gemm_fc_tc<<<grid, 256, smem_fc>>>(RES, WB + 0 * D * D, fc_b, H, M);

    fill_kernel<<<(E + 255) / 256, 256>>>(src, dst, CUR, CSR, E);

    const float beta1 = logf(2.0f);
    const float beta2 = logf(1.5f);

    agg_kernel<<<M, 128>>>(H, NORM, OFF, CSR, F);
    gemm_layer_tc<<<grid, 256, smem_layer>>>(F, H, WB + 1 * D * D, WB + 2 * D * D,
                                             b_1, RES, M, beta1);

    agg_kernel<<<M, 128>>>(RES, NORM, OFF, CSR, F);
    gemm_layer_tc<<<grid, 256, smem_layer>>>(F, H, WB + 3 * D * D, WB + 4 * D * D,
                                             b_2, out, M, beta2);
}

// round 7
// speedup vs baseline: 4.8392x; 1.2441x over previous
#include <cuda_runtime.h>
#include <cstdint>
#include <math.h>

#define NMAX 20000
#define EMAX 320000
#define D 512

// ---------------- scratch (static device globals; no allocation) -------------
__device__ float g_H   [NMAX * D];
__device__ float g_F   [NMAX * D];
__device__ float g_RES [NMAX * D];
__device__ float g_WB  [5 * D * D];     // tf32-rounded weights (fc: [N][K]; layers: [K][N] n-major)
__device__ float g_norm[NMAX];
__device__ int   g_cnt [NMAX];
__device__ int   g_off [NMAX + 1];
__device__ int   g_cur [NMAX + 1];
__device__ int   g_csr [EMAX];

// ================= small helpers ==============================================
__device__ __forceinline__ unsigned f2tf(float x)
{
    unsigned r;
    asm("cvt.rna.tf32.f32 %0, %1;" : "=r"(r) : "f"(x));
    return r;
}
__device__ __forceinline__ float rndtf(float x) { return __uint_as_float(f2tf(x)); }

__device__ __forceinline__ void cp16(uint32_t dst, const float* src, int bytes)
{
    asm volatile("cp.async.cg.shared.global [%0], [%1], 16, %2;"
                 :: "r"(dst), "l"(src), "r"(bytes));
}
__device__ __forceinline__ void cp_commit() { asm volatile("cp.async.commit_group;"); }
template <int N> __device__ __forceinline__ void cp_wait()
{ asm volatile("cp.async.wait_group %0;" :: "n"(N)); }

__device__ __forceinline__ void mma8(float* c,
                                     unsigned a0, unsigned a1, unsigned a2, unsigned a3,
                                     unsigned b0, unsigned b1)
{
    asm volatile(
        "mma.sync.aligned.m16n8k8.row.col.f32.tf32.tf32.f32 "
        "{%0,%1,%2,%3},{%4,%5,%6,%7},{%8,%9},{%0,%1,%2,%3};"
        : "+f"(c[0]), "+f"(c[1]), "+f"(c[2]), "+f"(c[3])
        : "r"(a0), "r"(a1), "r"(a2), "r"(a3), "r"(b0), "r"(b1));
}

// ================= weight prep ===============================================
// slot0: fc_w already [N][K]; slots 1-4: transpose NOT needed for layer path
// (layer B staged row-major [k][n]), just round + bake 0.1 into W2.
__global__ void prep_w(const float* __restrict__ fcw, const float* __restrict__ w11,
                       const float* __restrict__ w21, const float* __restrict__ w12,
                       const float* __restrict__ w22, float* __restrict__ wb)
{
    int i = blockIdx.x * blockDim.x + threadIdx.x;
    if (i >= 5 * D * D) return;
    int m = i >> 18;
    int o = i & (D * D - 1);
    const float* s;
    float sc = 1.0f;
    if      (m == 0)  s = fcw;
    else if (m == 1)  s = w11;
    else if (m == 2) { s = w21; sc = 0.1f; }
    else if (m == 3)  s = w12;
    else             { s = w22; sc = 0.1f; }
    wb[i] = rndtf(s[o] * sc);
}

// ================= CSR build ==================================================
__global__ void deg_kernel(const int* __restrict__ dst, int* __restrict__ cnt, int E)
{
    int i = blockIdx.x * blockDim.x + threadIdx.x;
    if (i < E) atomicAdd(cnt + __ldg(dst + i), 1);
}

// vectorized scan + cur + norm
__global__ void scan_kernel(const int* __restrict__ cnt, int* __restrict__ off,
                            int* __restrict__ cur, float* __restrict__ norm, int n)
{
    __shared__ int sh[1024];
    const int CH = 20;
    int t = threadIdx.x;
    int base = t * CH;
    int v[CH];
    if (base + CH <= n && (base & 3) == 0) {
        #pragma unroll
        for (int i = 0; i < CH / 4; i++) {
            int4 q = *reinterpret_cast<const int4*>(cnt + base + i * 4);
            v[i * 4 + 0] = q.x; v[i * 4 + 1] = q.y;
            v[i * 4 + 2] = q.z; v[i * 4 + 3] = q.w;
        }
    } else {
        #pragma unroll
        for (int i = 0; i < CH; i++) v[i] = (base + i < n) ? cnt[base + i] : 0;
    }
    int s = 0;
    #pragma unroll
    for (int i = 0; i < CH; i++) s += v[i];
    sh[t] = s;
    __syncthreads();
    for (int d = 1; d < 1024; d <<= 1) {
        int x = (t >= d) ? sh[t - d] : 0;
        __syncthreads();
        sh[t] += x;
        __syncthreads();
    }
    int run = sh[t] - s;
    #pragma unroll
    for (int i = 0; i < CH; i++) {
        int idx = base + i;
        if (idx < n) {
            off[idx] = run;
            cur[idx] = run;
            norm[idx] = rsqrtf(fmaxf((float)v[i], 1.0f));
            run += v[i];
        }
    }
    if (t == 1023) off[n] = sh[1023];
}

__global__ void fill_kernel(const int* __restrict__ src, const int* __restrict__ dst,
                            int* __restrict__ cur, int* __restrict__ csr, int E)
{
    int i = blockIdx.x * blockDim.x + threadIdx.x;
    if (i < E) {
        int d = __ldg(dst + i);
        int p = atomicAdd(cur + d, 1);
        csr[p] = __ldg(src + i);
    }
}

// ================= aggregation (CSR gather-reduce, fused norms) ===============
// F[n,:] = rndtf( 0.9 * norm[n] * sum norm[src]*h[src,:] )
__global__ __launch_bounds__(128)
void agg_kernel(const float* __restrict__ h, const float* __restrict__ norm,
                const int* __restrict__ off, const int* __restrict__ csr,
                float* __restrict__ F)
{
    int node = blockIdx.x;
    int c    = threadIdx.x * 4;
    int s0 = __ldg(off + node);
    int s1 = __ldg(off + node + 1);
    float4 acc = make_float4(0.f, 0.f, 0.f, 0.f);
    int j = s0;
    for (; j + 3 < s1; j += 4) {
        int   si[4];
        float wi[4];
        #pragma unroll
        for (int u = 0; u < 4; u++) si[u] = __ldg(csr + j + u);
        #pragma unroll
        for (int u = 0; u < 4; u++) wi[u] = __ldg(norm + si[u]);
        float4 v[4];
        #pragma unroll
        for (int u = 0; u < 4; u++)
            v[u] = *reinterpret_cast<const float4*>(h + (size_t)si[u] * D + c);
        #pragma unroll
        for (int u = 0; u < 4; u++) {
            acc.x += wi[u] * v[u].x;
            acc.y += wi[u] * v[u].y;
            acc.z += wi[u] * v[u].z;
            acc.w += wi[u] * v[u].w;
        }
    }
    for (; j < s1; j++) {
        int sA = __ldg(csr + j);
        float wA = __ldg(norm + sA);
        float4 vA = *reinterpret_cast<const float4*>(h + (size_t)sA * D + c);
        acc.x += wA * vA.x; acc.y += wA * vA.y;
        acc.z += wA * vA.z; acc.w += wA * vA.w;
    }
    float wn = __ldg(norm + node) * 0.9f;
    float4 r;
    r.x = rndtf(acc.x * wn);
    r.y = rndtf(acc.y * wn);
    r.z = rndtf(acc.z * wn);
    r.w = rndtf(acc.w * wn);
    *reinterpret_cast<float4*>(F + (size_t)node * D + c) = r;
}

// ================= tf32 mma.sync GEMMs, cp.async, K-chunk 32, 3 stages =======
// A tile: 128 rows x 32 k. Chunk (16B) swizzle: c' = c ^ (row & 7).
// Stage elems: A 4096; B_fc 4096 ([n][k], same layout); B_layer 4352 ([k][n], stride 136).
#define STG 3
#define AE 4096
#define BE_L 4352

// ---- gemm_fc: H = feat @ fc_w^T + bias (H raw fp32) -------------------------
__global__ __launch_bounds__(256, 2)
void gemm_fc_tc(const float* __restrict__ A, const float* __restrict__ Bw,
                const float* __restrict__ bias, float* __restrict__ C, int M)
{
    extern __shared__ unsigned sm[];
    const int tid = threadIdx.x, lane = tid & 31, warp = tid >> 5;
    const int wm = warp >> 2, wn = warp & 3;
    const int bm = blockIdx.y * 128, bn = blockIdx.x * 128;
    const int grp = lane >> 2, tig = lane & 3;
    const uint32_t smb = (uint32_t)__cvta_generic_to_shared(sm);

    float acc[4][4][4] = {};

    // loaders: 1024 chunks per tile, 4 per thread
    int lrow[4], lc[4];
    uint32_t dA[4], dB[4];
    int avalid[4];
    #pragma unroll
    for (int i = 0; i < 4; i++) {
        int cid = tid + i * 256;
        lrow[i] = cid >> 3;
        lc[i]   = cid & 7;
        int cs  = lc[i] ^ (lrow[i] & 7);
        dA[i] = smb + (uint32_t)(lrow[i] * 32 + cs * 4) * 4u;
        dB[i] = dA[i] + STG * AE * 4u;
        avalid[i] = (bm + lrow[i] < M) ? 16 : 0;
    }

    auto issue = [&](int stage, int k0) {
        uint32_t so = (uint32_t)stage * AE * 4u;
        #pragma unroll
        for (int i = 0; i < 4; i++) {
            const float* as = A + (size_t)(avalid[i] ? bm + lrow[i] : 0) * D + k0 + lc[i] * 4;
            cp16(dA[i] + so, as, avalid[i]);
            const float* bs = Bw + (size_t)(bn + lrow[i]) * D + k0 + lc[i] * 4;
            cp16(dB[i] + so, bs, 16);
        }
        cp_commit();
    };

    int abase[4], akey[4], bbase[4], bkey[4];
    #pragma unroll
    for (int mt = 0; mt < 4; mt++) {
        int r = wm * 64 + mt * 16 + grp;
        akey[mt]  = r & 7;
        abase[mt] = r * 32 + tig;
    }
    #pragma unroll
    for (int nt = 0; nt < 4; nt++) {
        int r = wn * 32 + nt * 8 + grp;
        bkey[nt]  = r & 7;
        bbase[nt] = r * 32 + tig;
    }

    auto compute = [&](int stage) {
        const unsigned* sA = sm + stage * AE;
        const unsigned* sB = sA + STG * AE;
        #pragma unroll
        for (int kc = 0; kc < 4; kc++) {
            unsigned af[4][4], bf[4][2];
            #pragma unroll
            for (int mt = 0; mt < 4; mt++) {
                int c0 = ((2 * kc) ^ akey[mt]) << 2;
                int c1 = ((2 * kc + 1) ^ akey[mt]) << 2;
                af[mt][0] = sA[abase[mt] + c0];
                af[mt][1] = sA[abase[mt] + 256 + c0];
                af[mt][2] = sA[abase[mt] + c1];
                af[mt][3] = sA[abase[mt] + 256 + c1];
            }
            #pragma unroll
            for (int nt = 0; nt < 4; nt++) {
                bf[nt][0] = sB[bbase[nt] + (((2 * kc) ^ bkey[nt]) << 2)];
                bf[nt][1] = sB[bbase[nt] + (((2 * kc + 1) ^ bkey[nt]) << 2)];
            }
            #pragma unroll
            for (int mt = 0; mt < 4; mt++)
                #pragma unroll
                for (int nt = 0; nt < 4; nt++)
                    mma8(acc[mt][nt], af[mt][0], af[mt][1], af[mt][2], af[mt][3],
                         bf[nt][0], bf[nt][1]);
        }
    };

    const int T = D / 32;     // 16
    issue(0, 0);
    issue(1, 32);
    for (int t = 0; t < T; t++) {
        cp_wait<STG - 2>();
        __syncthreads();
        if (t + STG - 1 < T) issue((t + STG - 1) % STG, (t + STG - 1) * 32);
        else                 cp_commit();
        compute(t % STG);
    }

    #pragma unroll
    for (int mt = 0; mt < 4; mt++) {
        int gr0 = bm + wm * 64 + mt * 16 + grp;
        int gr1 = gr0 + 8;
        #pragma unroll
        for (int nt = 0; nt < 4; nt++) {
            int gc = bn + wn * 32 + nt * 8 + tig * 2;
            float2 bb = *reinterpret_cast<const float2*>(bias + gc);
            if (gr0 < M) {
                float2 v = make_float2(acc[mt][nt][0] + bb.x, acc[mt][nt][1] + bb.y);
                *reinterpret_cast<float2*>(C + (size_t)gr0 * D + gc) = v;
            }
            if (gr1 < M) {
                float2 v = make_float2(acc[mt][nt][2] + bb.x, acc[mt][nt][3] + bb.y);
                *reinterpret_cast<float2*>(C + (size_t)gr1 * D + gc) = v;
            }
        }
    }
}

// ---- gemm_layer: R = relu( beta*(F@W1 + H0@W2s) + (1-beta)*(F+0.1*H0) + b ) -
__global__ __launch_bounds__(256, 2)
void gemm_layer_tc(const float* __restrict__ F, const float* __restrict__ H0,
                   const float* __restrict__ W1, const float* __restrict__ W2s,
                   const float* __restrict__ bias, float* __restrict__ R,
                   int M, float beta)
{
    extern __shared__ unsigned sm[];
    const int tid = threadIdx.x, lane = tid & 31, warp = tid >> 5;
    const int wm = warp >> 2, wn = warp & 3;
    const int bm = blockIdx.y * 128, bn = blockIdx.x * 128;
    const int grp = lane >> 2, tig = lane & 3;
    const uint32_t smb = (uint32_t)__cvta_generic_to_shared(sm);

    float acc[4][4][4] = {};

    // A loader (4 chunks), B loader ([k][n]: krow = cid>>5, chunk = cid&31)
    int lrow[4], lc[4], avalid[4];
    uint32_t dA[4], dB[4];
    int bkr[4], bcc[4];
    #pragma unroll
    for (int i = 0; i < 4; i++) {
        int cid = tid + i * 256;
        lrow[i] = cid >> 3;
        lc[i]   = cid & 7;
        int cs  = lc[i] ^ (lrow[i] & 7);
        dA[i] = smb + (uint32_t)(lrow[i] * 32 + cs * 4) * 4u;
        avalid[i] = (bm + lrow[i] < M) ? 16 : 0;
        bkr[i] = cid >> 5;
        bcc[i] = cid & 31;
        dB[i] = smb + STG * AE * 4u + (uint32_t)(bkr[i] * 136 + bcc[i] * 4) * 4u;
    }

    auto issue = [&](int stage, int t) {
        const bool second = (t >= 16);
        const float* Ap = second ? H0 : F;
        const float* Bp = second ? W2s : W1;
        const int k0 = (t & 15) * 32;
        uint32_t soA = (uint32_t)stage * AE * 4u;
        uint32_t soB = (uint32_t)stage * BE_L * 4u;
        #pragma unroll
        for (int i = 0; i < 4; i++) {
            const float* as = Ap + (size_t)(avalid[i] ? bm + lrow[i] : 0) * D + k0 + lc[i] * 4;
            cp16(dA[i] + soA, as, avalid[i]);
            const float* bs = Bp + (size_t)(k0 + bkr[i]) * D + bn + bcc[i] * 4;
            cp16(dB[i] + soB, bs, 16);
        }
        cp_commit();
    };

    int abase[4], akey[4], bbase[4];
    #pragma unroll
    for (int mt = 0; mt < 4; mt++) {
        int r = wm * 64 + mt * 16 + grp;
        akey[mt]  = r & 7;
        abase[mt] = r * 32 + tig;
    }
    #pragma unroll
    for (int nt = 0; nt < 4; nt++)
        bbase[nt] = wn * 32 + nt * 8 + grp;

    auto compute = [&](int stage) {
        const unsigned* sA = sm + stage * AE;
        const unsigned* sB = sm + STG * AE + stage * BE_L;
        #pragma unroll
        for (int kc = 0; kc < 4; kc++) {
            unsigned af[4][4], bf[4][2];
            #pragma unroll
            for (int mt = 0; mt < 4; mt++) {
                int c0 = ((2 * kc) ^ akey[mt]) << 2;
                int c1 = ((2 * kc + 1) ^ akey[mt]) << 2;
                af[mt][0] = sA[abase[mt] + c0];
                af[mt][1] = sA[abase[mt] + 256 + c0];
                af[mt][2] = sA[abase[mt] + c1];
                af[mt][3] = sA[abase[mt] + 256 + c1];
            }
            const unsigned* bk0 = sB + (kc * 8 + tig) * 136;
            #pragma unroll
            for (int nt = 0; nt < 4; nt++) {
                bf[nt][0] = bk0[bbase[nt]];
                bf[nt][1] = bk0[4 * 136 + bbase[nt]];
            }
            #pragma unroll
            for (int mt = 0; mt < 4; mt++)
                #pragma unroll
                for (int nt = 0; nt < 4; nt++)
                    mma8(acc[mt][nt], af[mt][0], af[mt][1], af[mt][2], af[mt][3],
                         bf[nt][0], bf[nt][1]);
        }
    };

    const int T = 2 * (D / 32);   // 32
    issue(0, 0);
    issue(1, 1);
    for (int t = 0; t < T; t++) {
        cp_wait<STG - 2>();
        __syncthreads();
        if (t + STG - 1 < T) issue((t + STG - 1) % STG, t + STG - 1);
        else                 cp_commit();
        compute(t % STG);
    }

    const float ob = 1.0f - beta;
    #pragma unroll
    for (int mt = 0; mt < 4; mt++) {
        int gr[2];
        gr[0] = bm + wm * 64 + mt * 16 + grp;
        gr[1] = gr[0] + 8;
        #pragma unroll
        for (int nt = 0; nt < 4; nt++) {
            int gc = bn + wn * 32 + nt * 8 + tig * 2;
            float2 bb = *reinterpret_cast<const float2*>(bias + gc);
            #pragma unroll
            for (int hh = 0; hh < 2; hh++) {
                if (gr[hh] >= M) continue;
                size_t base = (size_t)gr[hh] * D + gc;
                float2 f  = *reinterpret_cast<const float2*>(F  + base);
                float2 h0 = *reinterpret_cast<const float2*>(H0 + base);
                float2 v;
                v.x = fmaxf(beta * acc[mt][nt][2 * hh + 0] + ob * (f.x + 0.1f * h0.x) + bb.x, 0.f);
                v.y = fmaxf(beta * acc[mt][nt][2 * hh + 1] + ob * (f.y + 0.1f * h0.y) + bb.y, 0.f);
                *reinterpret_cast<float2*>(R + base) = v;
            }
        }
    }
}

// ================= host orchestration =========================================
extern "C" void kernel_launch(void* const* d_in, const int* in_sizes, int n_in,
                              void* d_out, int out_size)
{
    const float* feat = (const float*)d_in[0];
    const int*   src  = (const int*)  d_in[1];
    const int*   dst  = (const int*)  d_in[2];
    const float* fc_w = (const float*)d_in[3];
    const float* fc_b = (const float*)d_in[4];
    const float* w1_1 = (const float*)d_in[5];
    const float* w2_1 = (const float*)d_in[6];
    const float* b_1  = (const float*)d_in[7];
    const float* w1_2 = (const float*)d_in[8];
    const float* w2_2 = (const float*)d_in[9];
    const float* b_2  = (const float*)d_in[10];
    float* out = (float*)d_out;

    int M = in_sizes[0] / D;
    int E = in_sizes[1];

    float *H, *F, *RES, *WB, *NORM;
    int *CNT, *OFF, *CUR, *CSR;
    cudaGetSymbolAddress((void**)&H,    g_H);
    cudaGetSymbolAddress((void**)&F,    g_F);
    cudaGetSymbolAddress((void**)&RES,  g_RES);
    cudaGetSymbolAddress((void**)&WB,   g_WB);
    cudaGetSymbolAddress((void**)&NORM, g_norm);
    cudaGetSymbolAddress((void**)&CNT,  g_cnt);
    cudaGetSymbolAddress((void**)&OFF,  g_off);
    cudaGetSymbolAddress((void**)&CUR,  g_cur);
    cudaGetSymbolAddress((void**)&CSR,  g_csr);

    const int smem_fc    = STG * AE * 2 * 4;          // 98304
    const int smem_layer = STG * (AE + BE_L) * 4;     // 101376
    cudaFuncSetAttribute(gemm_fc_tc,    cudaFuncAttributeMaxDynamicSharedMemorySize, smem_fc);
    cudaFuncSetAttribute(gemm_layer_tc, cudaFuncAttributeMaxDynamicSharedMemorySize, smem_layer);

    dim3 grid(D / 128, (M + 127) / 128);

    cudaMemsetAsync(CNT, 0, (size_t)M * sizeof(int));
    deg_kernel<<<(E + 255) / 256, 256>>>(dst, CNT, E);
    prep_w<<<(5 * D * D + 255) / 256, 256>>>(fc_w, w1_1, w2_1, w1_2, w2_2, WB);
    scan_kernel<<<1, 1024>>>(CNT, OFF, CUR, NORM, M);

    gemm_fc_tc<<<grid, 256, smem_fc>>>(feat, WB + 0 * D * D, fc_b, H, M);

    fill_kernel<<<(E + 255) / 256, 256>>>(src, dst, CUR, CSR, E);

    const float beta1 = logf(2.0f);
    const float beta2 = logf(1.5f);

    agg_kernel<<<M, 128>>>(H, NORM, OFF, CSR, F);
    gemm_layer_tc<<<grid, 256, smem_layer>>>(F, H, WB + 1 * D * D, WB + 2 * D * D,
                                             b_1, RES, M, beta1);

    agg_kernel<<<M, 128>>>(RES, NORM, OFF, CSR, F);
    gemm_layer_tc<<<grid, 256, smem_layer>>>(F, H, WB + 3 * D * D, WB + 4 * D * D,
                                             b_2, out, M, beta2);
}

// round 8
// speedup vs baseline: 5.2155x; 1.0778x over previous
#include <cuda_runtime.h>
#include <cstdint>
#include <math.h>

#define NMAX 20000
#define EMAX 320000
#define D 512

// ---------------- scratch (static device globals; no allocation) -------------
__device__ float g_H   [NMAX * D];
__device__ float g_F   [NMAX * D];
__device__ float g_RES [NMAX * D];
__device__ float g_WB  [5 * D * D];     // tf32-rounded weights, ALL [N][K] K-major
__device__ float g_norm[NMAX];
__device__ int   g_cnt [NMAX];
__device__ int   g_off [NMAX + 1];
__device__ int   g_cur [NMAX + 1];
__device__ int   g_csr [EMAX];

// ================= small helpers ==============================================
__device__ __forceinline__ unsigned f2tf(float x)
{
    unsigned r;
    asm("cvt.rna.tf32.f32 %0, %1;" : "=r"(r) : "f"(x));
    return r;
}
__device__ __forceinline__ float rndtf(float x) { return __uint_as_float(f2tf(x)); }

__device__ __forceinline__ void cp16(uint32_t dst, const float* src, int bytes)
{
    asm volatile("cp.async.cg.shared.global [%0], [%1], 16, %2;"
                 :: "r"(dst), "l"(src), "r"(bytes));
}
__device__ __forceinline__ void cp_commit() { asm volatile("cp.async.commit_group;"); }
template <int N> __device__ __forceinline__ void cp_wait()
{ asm volatile("cp.async.wait_group %0;" :: "n"(N)); }

__device__ __forceinline__ void mma8(float* c,
                                     unsigned a0, unsigned a1, unsigned a2, unsigned a3,
                                     unsigned b0, unsigned b1)
{
    asm volatile(
        "mma.sync.aligned.m16n8k8.row.col.f32.tf32.tf32.f32 "
        "{%0,%1,%2,%3},{%4,%5,%6,%7},{%8,%9},{%0,%1,%2,%3};"
        : "+f"(c[0]), "+f"(c[1]), "+f"(c[2]), "+f"(c[3])
        : "r"(a0), "r"(a1), "r"(a2), "r"(a3), "r"(b0), "r"(b1));
}

__device__ __forceinline__ void ldsm4(unsigned& r0, unsigned& r1, unsigned& r2, unsigned& r3,
                                      uint32_t addr)
{
    asm volatile("ldmatrix.sync.aligned.m8n8.x4.shared.b16 {%0,%1,%2,%3}, [%4];"
                 : "=r"(r0), "=r"(r1), "=r"(r2), "=r"(r3) : "r"(addr));
}

// ================= weight prep ===============================================
// slot0: fc_w already [N][K] -> just round.
__global__ void prep_fc(const float* __restrict__ fcw, float* __restrict__ wb)
{
    int i = blockIdx.x * blockDim.x + threadIdx.x;
    if (i < D * D) wb[i] = rndtf(fcw[i]);
}

// slots 1-4: layer weights stored [K][N]; transpose to [N][K], round, scale W2 by 0.1
__global__ void prep_wT(const float* __restrict__ w11, const float* __restrict__ w21,
                        const float* __restrict__ w12, const float* __restrict__ w22,
                        float* __restrict__ wb)
{
    __shared__ float tile[32][33];
    int mat = blockIdx.z;
    const float* s;
    float sc = 1.0f;
    if      (mat == 0)  s = w11;
    else if (mat == 1) { s = w21; sc = 0.1f; }
    else if (mat == 2)  s = w12;
    else               { s = w22; sc = 0.1f; }
    float* dst = wb + (mat + 1) * D * D;

    int tx = threadIdx.x, ty = threadIdx.y;
    int k0 = blockIdx.y * 32, n0 = blockIdx.x * 32;
    #pragma unroll
    for (int j = 0; j < 4; j++)
        tile[ty + j * 8][tx] = s[(size_t)(k0 + ty + j * 8) * D + n0 + tx];
    __syncthreads();
    #pragma unroll
    for (int j = 0; j < 4; j++)
        dst[(size_t)(n0 + ty + j * 8) * D + k0 + tx] = rndtf(tile[tx][ty + j * 8] * sc);
}

// ================= CSR build ==================================================
__global__ void deg_kernel(const int* __restrict__ dst, int* __restrict__ cnt, int E)
{
    int i = blockIdx.x * blockDim.x + threadIdx.x;
    if (i < E) atomicAdd(cnt + __ldg(dst + i), 1);
}

__global__ void scan_kernel(const int* __restrict__ cnt, int* __restrict__ off,
                            int* __restrict__ cur, float* __restrict__ norm, int n)
{
    __shared__ int sh[1024];
    const int CH = 20;
    int t = threadIdx.x;
    int base = t * CH;
    int v[CH];
    if (base + CH <= n && (base & 3) == 0) {
        #pragma unroll
        for (int i = 0; i < CH / 4; i++) {
            int4 q = *reinterpret_cast<const int4*>(cnt + base + i * 4);
            v[i * 4 + 0] = q.x; v[i * 4 + 1] = q.y;
            v[i * 4 + 2] = q.z; v[i * 4 + 3] = q.w;
        }
    } else {
        #pragma unroll
        for (int i = 0; i < CH; i++) v[i] = (base + i < n) ? cnt[base + i] : 0;
    }
    int s = 0;
    #pragma unroll
    for (int i = 0; i < CH; i++) s += v[i];
    sh[t] = s;
    __syncthreads();
    for (int d = 1; d < 1024; d <<= 1) {
        int x = (t >= d) ? sh[t - d] : 0;
        __syncthreads();
        sh[t] += x;
        __syncthreads();
    }
    int run = sh[t] - s;
    #pragma unroll
    for (int i = 0; i < CH; i++) {
        int idx = base + i;
        if (idx < n) {
            off[idx] = run;
            cur[idx] = run;
            norm[idx] = rsqrtf(fmaxf((float)v[i], 1.0f));
            run += v[i];
        }
    }
    if (t == 1023) off[n] = sh[1023];
}

__global__ void fill_kernel(const int* __restrict__ src, const int* __restrict__ dst,
                            int* __restrict__ cur, int* __restrict__ csr, int E)
{
    int i = blockIdx.x * blockDim.x + threadIdx.x;
    if (i < E) {
        int d = __ldg(dst + i);
        int p = atomicAdd(cur + d, 1);
        csr[p] = __ldg(src + i);
    }
}

// ================= aggregation (CSR gather-reduce, fused norms) ===============
__global__ __launch_bounds__(128)
void agg_kernel(const float* __restrict__ h, const float* __restrict__ norm,
                const int* __restrict__ off, const int* __restrict__ csr,
                float* __restrict__ F)
{
    int node = blockIdx.x;
    int c    = threadIdx.x * 4;
    int s0 = __ldg(off + node);
    int s1 = __ldg(off + node + 1);
    float4 acc = make_float4(0.f, 0.f, 0.f, 0.f);
    int j = s0;
    for (; j + 3 < s1; j += 4) {
        int   si[4];
        float wi[4];
        #pragma unroll
        for (int u = 0; u < 4; u++) si[u] = __ldg(csr + j + u);
        #pragma unroll
        for (int u = 0; u < 4; u++) wi[u] = __ldg(norm + si[u]);
        float4 v[4];
        #pragma unroll
        for (int u = 0; u < 4; u++)
            v[u] = *reinterpret_cast<const float4*>(h + (size_t)si[u] * D + c);
        #pragma unroll
        for (int u = 0; u < 4; u++) {
            acc.x += wi[u] * v[u].x;
            acc.y += wi[u] * v[u].y;
            acc.z += wi[u] * v[u].z;
            acc.w += wi[u] * v[u].w;
        }
    }
    for (; j < s1; j++) {
        int sA = __ldg(csr + j);
        float wA = __ldg(norm + sA);
        float4 vA = *reinterpret_cast<const float4*>(h + (size_t)sA * D + c);
        acc.x += wA * vA.x; acc.y += wA * vA.y;
        acc.z += wA * vA.z; acc.w += wA * vA.w;
    }
    float wn = __ldg(norm + node) * 0.9f;
    float4 r;
    r.x = rndtf(acc.x * wn);
    r.y = rndtf(acc.y * wn);
    r.z = rndtf(acc.z * wn);
    r.w = rndtf(acc.w * wn);
    *reinterpret_cast<float4*>(F + (size_t)node * D + c) = r;
}

// ================= unified tf32 GEMM (cp.async + ldmatrix) ===================
// A tile [128 rows][32 k], B tile [128 n][32 k]; 16B-chunk swizzle c' = c ^ (row&7).
#define STG 3
#define AE 4096

// LAYER=false: C = A0 @ B0^T(nk) + bias         (raw fp32 out)
// LAYER=true:  C = relu(beta*(A0@B0 + A1@B1) + (1-beta)*(A0f + 0.1*A1) + bias)
template <bool LAYER>
__global__ __launch_bounds__(256, 2)
void gemm_tc(const float* __restrict__ A0, const float* __restrict__ A1,
             const float* __restrict__ B0, const float* __restrict__ B1,
             const float* __restrict__ bias, float* __restrict__ C,
             int M, float beta)
{
    extern __shared__ unsigned sm[];
    const int tid = threadIdx.x, lane = tid & 31, warp = tid >> 5;
    const int wm = warp >> 2, wn = warp & 3;
    const int bm = blockIdx.y * 128, bn = blockIdx.x * 128;
    const uint32_t smb = (uint32_t)__cvta_generic_to_shared(sm);
    const uint32_t smbB = smb + STG * AE * 4u;

    float acc[4][4][4] = {};

    // ---- cp.async loaders: 1024 chunks/tile, 4/thread, same layout A and B --
    int lrow[4], lc[4], avalid[4];
    uint32_t dA[4], dB[4];
    #pragma unroll
    for (int i = 0; i < 4; i++) {
        int cid = tid + i * 256;
        lrow[i] = cid >> 3;
        lc[i]   = cid & 7;
        int cs  = lc[i] ^ (lrow[i] & 7);
        dA[i] = smb  + (uint32_t)(lrow[i] * 32 + cs * 4) * 4u;
        dB[i] = dA[i] + STG * AE * 4u;
        avalid[i] = (bm + lrow[i] < M) ? 16 : 0;
    }

    auto issue = [&](int stage, int t) {
        const float* Ap;
        const float* Bp;
        int k0;
        if (LAYER) {
            bool second = (t >= 16);
            Ap = second ? A1 : A0;
            Bp = second ? B1 : B0;
            k0 = (t & 15) * 32;
        } else {
            Ap = A0; Bp = B0; k0 = t * 32;
        }
        uint32_t so = (uint32_t)stage * AE * 4u;
        #pragma unroll
        for (int i = 0; i < 4; i++) {
            const float* as = Ap + (size_t)(avalid[i] ? bm + lrow[i] : 0) * D + k0 + lc[i] * 4;
            cp16(dA[i] + so, as, avalid[i]);
            const float* bs = Bp + (size_t)(bn + lrow[i]) * D + k0 + lc[i] * 4;
            cp16(dB[i] + so, bs, 16);
        }
        cp_commit();
    };

    // ---- ldmatrix lane-address precompute -----------------------------------
    // A tiles per (mt,kc): lanes 0-7 rows lo/k-lo, 8-15 rows hi/k-lo,
    //                      16-23 rows lo/k-hi, 24-31 rows hi/k-hi
    const int hiA = (lane >> 4) & 1;
    uint32_t abase[4];
    int akey[4];
    #pragma unroll
    for (int mt = 0; mt < 4; mt++) {
        int row = wm * 64 + mt * 16 + (lane & 15);
        akey[mt]  = row & 7;
        abase[mt] = (uint32_t)row * 128u;
    }
    // B tiles per (np,kc): lanes 0-7 n-blk0/k-lo, 8-15 n-blk0/k-hi,
    //                      16-23 n-blk1/k-lo, 24-31 n-blk1/k-hi
    const int hiB = (lane >> 3) & 1;
    uint32_t bbase[2];
    int bkey[2];
    #pragma unroll
    for (int np = 0; np < 2; np++) {
        int row = wn * 32 + np * 16 + (lane & 7) + ((lane & 16) ? 8 : 0);
        bkey[np]  = row & 7;
        bbase[np] = (uint32_t)row * 128u;
    }

    auto compute = [&](int stage) {
        uint32_t sa = smb  + (uint32_t)stage * AE * 4u;
        uint32_t sb = smbB + (uint32_t)stage * AE * 4u;
        #pragma unroll
        for (int kc = 0; kc < 4; kc++) {
            unsigned af[4][4], bf[4][2];
            #pragma unroll
            for (int mt = 0; mt < 4; mt++) {
                uint32_t addr = sa + abase[mt] + (uint32_t)(((2 * kc + hiA) ^ akey[mt]) << 4);
                ldsm4(af[mt][0], af[mt][1], af[mt][2], af[mt][3], addr);
            }
            #pragma unroll
            for (int np = 0; np < 2; np++) {
                uint32_t addr = sb + bbase[np] + (uint32_t)(((2 * kc + hiB) ^ bkey[np]) << 4);
                ldsm4(bf[2 * np][0], bf[2 * np][1], bf[2 * np + 1][0], bf[2 * np + 1][1], addr);
            }
            #pragma unroll
            for (int mt = 0; mt < 4; mt++)
                #pragma unroll
                for (int nt = 0; nt < 4; nt++)
                    mma8(acc[mt][nt], af[mt][0], af[mt][1], af[mt][2], af[mt][3],
                         bf[nt][0], bf[nt][1]);
        }
    };

    const int T = LAYER ? 32 : 16;
    issue(0, 0);
    issue(1, 1);
    for (int t = 0; t < T; t++) {
        cp_wait<STG - 2>();
        __syncthreads();
        if (t + STG - 1 < T) issue((t + STG - 1) % STG, t + STG - 1);
        else                 cp_commit();
        compute(t % STG);
    }

    // ---- epilogue -----------------------------------------------------------
    const int grp = lane >> 2, tig = lane & 3;
    const float ob = 1.0f - beta;
    #pragma unroll
    for (int mt = 0; mt < 4; mt++) {
        int gr[2];
        gr[0] = bm + wm * 64 + mt * 16 + grp;
        gr[1] = gr[0] + 8;
        #pragma unroll
        for (int nt = 0; nt < 4; nt++) {
            int gc = bn + wn * 32 + nt * 8 + tig * 2;
            float2 bb = *reinterpret_cast<const float2*>(bias + gc);
            #pragma unroll
            for (int hh = 0; hh < 2; hh++) {
                if (gr[hh] >= M) continue;
                size_t base = (size_t)gr[hh] * D + gc;
                float2 v;
                if (LAYER) {
                    float2 f  = *reinterpret_cast<const float2*>(A0 + base);
                    float2 h0 = *reinterpret_cast<const float2*>(A1 + base);
                    v.x = fmaxf(beta * acc[mt][nt][2 * hh + 0] + ob * (f.x + 0.1f * h0.x) + bb.x, 0.f);
                    v.y = fmaxf(beta * acc[mt][nt][2 * hh + 1] + ob * (f.y + 0.1f * h0.y) + bb.y, 0.f);
                } else {
                    v.x = acc[mt][nt][2 * hh + 0] + bb.x;
                    v.y = acc[mt][nt][2 * hh + 1] + bb.y;
                }
                *reinterpret_cast<float2*>(C + base) = v;
            }
        }
    }
}

// ================= host orchestration =========================================
extern "C" void kernel_launch(void* const* d_in, const int* in_sizes, int n_in,
                              void* d_out, int out_size)
{
    const float* feat = (const float*)d_in[0];
    const int*   src  = (const int*)  d_in[1];
    const int*   dst  = (const int*)  d_in[2];
    const float* fc_w = (const float*)d_in[3];
    const float* fc_b = (const float*)d_in[4];
    const float* w1_1 = (const float*)d_in[5];
    const float* w2_1 = (const float*)d_in[6];
    const float* b_1  = (const float*)d_in[7];
    const float* w1_2 = (const float*)d_in[8];
    const float* w2_2 = (const float*)d_in[9];
    const float* b_2  = (const float*)d_in[10];
    float* out = (float*)d_out;

    int M = in_sizes[0] / D;
    int E = in_sizes[1];

    float *H, *F, *RES, *WB, *NORM;
    int *CNT, *OFF, *CUR, *CSR;
    cudaGetSymbolAddress((void**)&H,    g_H);
    cudaGetSymbolAddress((void**)&F,    g_F);
    cudaGetSymbolAddress((void**)&RES,  g_RES);
    cudaGetSymbolAddress((void**)&WB,   g_WB);
    cudaGetSymbolAddress((void**)&NORM, g_norm);
    cudaGetSymbolAddress((void**)&CNT,  g_cnt);
    cudaGetSymbolAddress((void**)&OFF,  g_off);
    cudaGetSymbolAddress((void**)&CUR,  g_cur);
    cudaGetSymbolAddress((void**)&CSR,  g_csr);

    const int smem = STG * AE * 2 * 4;   // 98304
    cudaFuncSetAttribute(gemm_tc<false>, cudaFuncAttributeMaxDynamicSharedMemorySize, smem);
    cudaFuncSetAttribute(gemm_tc<true>,  cudaFuncAttributeMaxDynamicSharedMemorySize, smem);

    dim3 grid(D / 128, (M + 127) / 128);

    cudaMemsetAsync(CNT, 0, (size_t)M * sizeof(int));
    deg_kernel<<<(E + 255) / 256, 256>>>(dst, CNT, E);
    prep_fc<<<(D * D + 255) / 256, 256>>>(fc_w, WB);
    prep_wT<<<dim3(16, 16, 4), dim3(32, 8)>>>(w1_1, w2_1, w1_2, w2_2, WB);
    scan_kernel<<<1, 1024>>>(CNT, OFF, CUR, NORM, M);

    gemm_tc<false><<<grid, 256, smem>>>(feat, nullptr, WB, nullptr, fc_b, H, M, 0.f);

    fill_kernel<<<(E + 255) / 256, 256>>>(src, dst, CUR, CSR, E);

    const float beta1 = logf(2.0f);
    const float beta2 = logf(1.5f);

    agg_kernel<<<M, 128>>>(H, NORM, OFF, CSR, F);
    gemm_tc<true><<<grid, 256, smem>>>(F, H, WB + 1 * D * D, WB + 2 * D * D,
                                       b_1, RES, M, beta1);

    agg_kernel<<<M, 128>>>(RES, NORM, OFF, CSR, F);
    gemm_tc<true><<<grid, 256, smem>>>(F, H, WB + 3 * D * D, WB + 4 * D * D,
                                       b_2, out, M, beta2);
}